// round 1
// baseline (speedup 1.0000x reference)
#include <cuda_runtime.h>

#define T_STEPS 200
#define BATCH   256
#define IN_F    512
#define H1      1024
#define H2      1024
#define H3      512

// ---------------- persistent device state (no allocations allowed) ----------
__device__ float g_m1[BATCH * H1];
__device__ float g_m2[BATCH * H2];
__device__ float g_m3[BATCH * H3];
__device__ float g_m3sum[BATCH * H3];
__device__ float g_spk1[BATCH * H1];
__device__ float g_spk2[BATCH * H2];
__device__ int   g_cnt[3];

// ---------------- init: zero state each launch (graph-replay safe) ---------
__global__ void init_kernel() {
    int idx = blockIdx.x * blockDim.x + threadIdx.x;
    if (idx < BATCH * H1) { g_m1[idx] = 0.f; g_m2[idx] = 0.f; }
    if (idx < BATCH * H3) { g_m3[idx] = 0.f; g_m3sum[idx] = 0.f; }
    if (idx < 3) g_cnt[idx] = 0;
}

// ---------------- fused GEMM (NT, fp32) + LIF epilogue ----------------------
// C[b,j] = dot(A[b,:], W[j,:]) + bias[j]   (both operands K-major row-major)
// then LIF: reset = (m>1); m = beta*m + C - reset; spk = (m>1)
template<int BM, int BN, int BK, int K, int H, bool HAS_SPK, bool HAS_SUM>
__global__ void layer_kernel(const float* __restrict__ A,
                             const float* __restrict__ W,
                             const float* __restrict__ bias,
                             float* __restrict__ mem,
                             float* __restrict__ spk,
                             float* __restrict__ msum,
                             int*   __restrict__ cnt,
                             float  beta)
{
    constexpr int TM = 4, TN = 4;
    constexpr int NTX = BN / TN;           // 16
    constexpr int NTY = BM / TM;           // 8
    constexpr int THREADS = NTX * NTY;     // 128

    __shared__ float As[BK][BM + 4];
    __shared__ float Ws[BK][BN + 4];

    const int tid = threadIdx.x;
    const int tx  = tid % NTX;
    const int ty  = tid / NTX;
    const int bn0 = blockIdx.x * BN;
    const int bm0 = blockIdx.y * BM;

    float acc[TM][TN];
#pragma unroll
    for (int i = 0; i < TM; i++)
#pragma unroll
        for (int j = 0; j < TN; j++) acc[i][j] = 0.f;

    for (int k0 = 0; k0 < K; k0 += BK) {
        // stage A tile [BM x BK], store transposed As[k][m]
#pragma unroll
        for (int i = tid * 4; i < BM * BK; i += THREADS * 4) {
            int r = i / BK, c = i % BK;
            float4 v = *(const float4*)(A + (size_t)(bm0 + r) * K + k0 + c);
            As[c + 0][r] = v.x; As[c + 1][r] = v.y;
            As[c + 2][r] = v.z; As[c + 3][r] = v.w;
        }
        // stage W tile [BN x BK], store transposed Ws[k][n]
#pragma unroll
        for (int i = tid * 4; i < BN * BK; i += THREADS * 4) {
            int r = i / BK, c = i % BK;
            float4 v = *(const float4*)(W + (size_t)(bn0 + r) * K + k0 + c);
            Ws[c + 0][r] = v.x; Ws[c + 1][r] = v.y;
            Ws[c + 2][r] = v.z; Ws[c + 3][r] = v.w;
        }
        __syncthreads();

#pragma unroll
        for (int k = 0; k < BK; k++) {
            float a[TM], w[TN];
            *(float4*)a = *(const float4*)&As[k][ty * TM];
            *(float4*)w = *(const float4*)&Ws[k][tx * TN];
#pragma unroll
            for (int i = 0; i < TM; i++)
#pragma unroll
                for (int j = 0; j < TN; j++)
                    acc[i][j] = fmaf(a[i], w[j], acc[i][j]);
        }
        __syncthreads();
    }

    // LIF epilogue — each thread owns its TMxTN outputs
    int myc = 0;
#pragma unroll
    for (int i = 0; i < TM; i++) {
        const int b = bm0 + ty * TM + i;
#pragma unroll
        for (int j = 0; j < TN; j++) {
            const int col = bn0 + tx * TN + j;
            const size_t idx = (size_t)b * H + col;
            float c = acc[i][j] + bias[col];
            float m = mem[idx];
            float reset = (m > 1.0f) ? 1.0f : 0.0f;   // spike(m_prev - 1)
            m = beta * m + c - reset;                  // subtract-reset
            float s = (m > 1.0f) ? 1.0f : 0.0f;       // spike(m_new - 1)
            mem[idx] = m;
            if (HAS_SPK) spk[idx] = s;
            if (HAS_SUM) msum[idx] += m;
            myc += (s > 0.f) ? 1 : 0;
        }
    }

    // exact integer spike count: warp reduce -> block reduce -> atomic
#pragma unroll
    for (int o = 16; o > 0; o >>= 1) myc += __shfl_down_sync(0xFFFFFFFFu, myc, o);
    __shared__ int sred[THREADS / 32];
    if ((tid & 31) == 0) sred[tid >> 5] = myc;
    __syncthreads();
    if (tid == 0) {
        int tot = 0;
#pragma unroll
        for (int w = 0; w < THREADS / 32; w++) tot += sred[w];
        atomicAdd(cnt, tot);
    }
}

// ---------------- readout: out = (m3sum/T) @ Wr^T + br ; stats --------------
__global__ void final_kernel(const float* __restrict__ Wr,
                             const float* __restrict__ br,
                             float* __restrict__ out)
{
    const int b = threadIdx.x;   // 256 threads, one batch row each
    float a0 = 0.f, a1 = 0.f;
    for (int j = 0; j < H3; j++) {
        float v = g_m3sum[(size_t)b * H3 + j] / (float)T_STEPS;
        a0 = fmaf(v, Wr[j],      a0);
        a1 = fmaf(v, Wr[H3 + j], a1);
    }
    out[b * 2 + 0] = a0 + br[0];
    out[b * 2 + 1] = a1 + br[1];

    if (b < 3) {
        float denom = (b == 0) ? (float)((double)T_STEPS * BATCH * H1)
                    : (b == 1) ? (float)((double)T_STEPS * BATCH * H2)
                               : (float)((double)T_STEPS * BATCH * H3);
        out[BATCH * 2 + b] = (float)g_cnt[b] / denom;
    }
}

// ---------------- launch ----------------------------------------------------
extern "C" void kernel_launch(void* const* d_in, const int* in_sizes, int n_in,
                              void* d_out, int out_size)
{
    const float* spikes = (const float*)d_in[0];  // [200,256,512]
    const float* W1 = (const float*)d_in[1];      // [1024,512]
    const float* b1 = (const float*)d_in[2];
    const float* W2 = (const float*)d_in[3];      // [1024,1024]
    const float* b2 = (const float*)d_in[4];
    const float* W3 = (const float*)d_in[5];      // [512,1024]
    const float* b3 = (const float*)d_in[6];
    const float* Wr = (const float*)d_in[7];      // [2,512]
    const float* br = (const float*)d_in[8];
    float* out = (float*)d_out;

    float *pm1, *pm2, *pm3, *pms, *ps1, *ps2;
    int* pcnt;
    cudaGetSymbolAddress((void**)&pm1,  g_m1);
    cudaGetSymbolAddress((void**)&pm2,  g_m2);
    cudaGetSymbolAddress((void**)&pm3,  g_m3);
    cudaGetSymbolAddress((void**)&pms,  g_m3sum);
    cudaGetSymbolAddress((void**)&ps1,  g_spk1);
    cudaGetSymbolAddress((void**)&ps2,  g_spk2);
    cudaGetSymbolAddress((void**)&pcnt, g_cnt);

    const float BETA1 = 0.81873075307798182f;  // exp(-1/5)
    const float BETA2 = 0.90483741803595957f;  // exp(-1/10)
    const float BETA3 = 0.95122942450071402f;  // exp(-1/20)

    init_kernel<<<(BATCH * H1 + 255) / 256, 256>>>();

    for (int t = 0; t < T_STEPS; t++) {
        const float* x = spikes + (size_t)t * BATCH * IN_F;
        layer_kernel<32, 64, 32, IN_F, H1, true,  false>
            <<<dim3(H1 / 64, BATCH / 32), 128>>>(x,   W1, b1, pm1, ps1, nullptr, pcnt + 0, BETA1);
        layer_kernel<32, 64, 32, H1,   H2, true,  false>
            <<<dim3(H2 / 64, BATCH / 32), 128>>>(ps1, W2, b2, pm2, ps2, nullptr, pcnt + 1, BETA2);
        layer_kernel<32, 64, 32, H2,   H3, false, true>
            <<<dim3(H3 / 64, BATCH / 32), 128>>>(ps2, W3, b3, pm3, nullptr, pms,  pcnt + 2, BETA3);
    }

    final_kernel<<<1, 256>>>(Wr, br, out);
}

// round 3
// speedup vs baseline: 2.3226x; 2.3226x over previous
#include <cuda_runtime.h>

#define T_STEPS 200
#define BATCH   256
#define IN_F    512
#define H1      1024
#define H2      1024
#define H3      512

// ---------------- persistent device state (no allocations allowed) ----------
__device__ float g_m1[BATCH * H1];
__device__ float g_m2[BATCH * H2];
__device__ float g_m3[BATCH * H3];
__device__ float g_m3sum[BATCH * H3];
__device__ float g_spk1[BATCH * H1];
__device__ float g_spk2[BATCH * H2];
__device__ int   g_cnt[3];

// ---------------- init: zero state each launch (graph-replay safe) ---------
__global__ void init_kernel() {
    int idx = blockIdx.x * blockDim.x + threadIdx.x;
    if (idx < BATCH * H1) { g_m1[idx] = 0.f; g_m2[idx] = 0.f; }
    if (idx < BATCH * H3) { g_m3[idx] = 0.f; g_m3sum[idx] = 0.f; }
    if (idx < 3) g_cnt[idx] = 0;
}

// ---------------- fused GEMM (NT, fp32, double-buffered) + LIF epilogue -----
// C[b,j] = dot(A[b,:], W[j,:]) + bias[j]
// LIF: reset = (m>1); m = beta*m + C - reset; spk = (m>1)
template<int BM, int BN, int BK, int TM, int TN, int K, int H,
         bool HAS_SPK, bool HAS_SUM>
__global__ void __launch_bounds__(256)
layer_kernel(const float* __restrict__ A,
             const float* __restrict__ W,
             const float* __restrict__ bias,
             float* __restrict__ mem,
             float* __restrict__ spk,
             float* __restrict__ msum,
             int*   __restrict__ cnt,
             float  beta)
{
    constexpr int NTX = BN / TN;
    constexpr int NTY = BM / TM;
    constexpr int THREADS = NTX * NTY;
    static_assert(THREADS == 256, "expect 256 threads");
    constexpr int KT = K / BK;
    constexpr int A_V4 = (BM * BK) / (THREADS * 4);   // float4 per thread (A)
    constexpr int W_V4 = (BN * BK) / (THREADS * 4);   // float4 per thread (W)
    static_assert(A_V4 >= 1 && W_V4 >= 1, "tile too small");

    __shared__ float As[2][BK][BM + 4];   // 16B-aligned row stride
    __shared__ float Ws[2][BK][BN + 4];

    const int tid = threadIdx.x;
    const int tx  = tid % NTX;
    const int ty  = tid / NTX;
    const int bn0 = blockIdx.x * BN;
    const int bm0 = blockIdx.y * BM;

    float acc[TM][TN];
#pragma unroll
    for (int i = 0; i < TM; i++)
#pragma unroll
        for (int j = 0; j < TN; j++) acc[i][j] = 0.f;

    // staging index precompute (float4 granularity)
    int ar[A_V4], ac[A_V4], wr[W_V4], wc[W_V4];
#pragma unroll
    for (int v = 0; v < A_V4; v++) {
        int flat = (tid + v * THREADS) * 4;
        ar[v] = flat / BK;  ac[v] = flat % BK;
    }
#pragma unroll
    for (int v = 0; v < W_V4; v++) {
        int flat = (tid + v * THREADS) * 4;
        wr[v] = flat / BK;  wc[v] = flat % BK;
    }

    float4 aReg[A_V4], wReg[W_V4];

    // ---- prologue: tile 0 straight to smem buffer 0 ----
#pragma unroll
    for (int v = 0; v < A_V4; v++)
        aReg[v] = *(const float4*)(A + (size_t)(bm0 + ar[v]) * K + ac[v]);
#pragma unroll
    for (int v = 0; v < W_V4; v++)
        wReg[v] = *(const float4*)(W + (size_t)(bn0 + wr[v]) * K + wc[v]);
#pragma unroll
    for (int v = 0; v < A_V4; v++) {
        As[0][ac[v] + 0][ar[v]] = aReg[v].x;  As[0][ac[v] + 1][ar[v]] = aReg[v].y;
        As[0][ac[v] + 2][ar[v]] = aReg[v].z;  As[0][ac[v] + 3][ar[v]] = aReg[v].w;
    }
#pragma unroll
    for (int v = 0; v < W_V4; v++) {
        Ws[0][wc[v] + 0][wr[v]] = wReg[v].x;  Ws[0][wc[v] + 1][wr[v]] = wReg[v].y;
        Ws[0][wc[v] + 2][wr[v]] = wReg[v].z;  Ws[0][wc[v] + 3][wr[v]] = wReg[v].w;
    }
    __syncthreads();

    int buf = 0;
    for (int kt = 0; kt < KT; kt++) {
        // prefetch next tile into registers (overlaps with compute below)
        if (kt + 1 < KT) {
            const int k0 = (kt + 1) * BK;
#pragma unroll
            for (int v = 0; v < A_V4; v++)
                aReg[v] = *(const float4*)(A + (size_t)(bm0 + ar[v]) * K + k0 + ac[v]);
#pragma unroll
            for (int v = 0; v < W_V4; v++)
                wReg[v] = *(const float4*)(W + (size_t)(bn0 + wr[v]) * K + k0 + wc[v]);
        }

        // compute on current buffer
#pragma unroll
        for (int k = 0; k < BK; k++) {
            float a[TM], w[TN];
            if constexpr (TM == 2) {
                float2 t = *(const float2*)&As[buf][k][ty * 2];
                a[0] = t.x; a[1] = t.y;
            } else {
                float4 t = *(const float4*)&As[buf][k][ty * 4];
                a[0] = t.x; a[1] = t.y; a[2] = t.z; a[3] = t.w;
            }
            if constexpr (TN == 2) {
                float2 t = *(const float2*)&Ws[buf][k][tx * 2];
                w[0] = t.x; w[1] = t.y;
            } else {
                float4 t = *(const float4*)&Ws[buf][k][tx * 4];
                w[0] = t.x; w[1] = t.y; w[2] = t.z; w[3] = t.w;
            }
#pragma unroll
            for (int i = 0; i < TM; i++)
#pragma unroll
                for (int j = 0; j < TN; j++)
                    acc[i][j] = fmaf(a[i], w[j], acc[i][j]);
        }

        // store prefetched tile into other buffer
        if (kt + 1 < KT) {
            const int nb = buf ^ 1;
#pragma unroll
            for (int v = 0; v < A_V4; v++) {
                As[nb][ac[v] + 0][ar[v]] = aReg[v].x;  As[nb][ac[v] + 1][ar[v]] = aReg[v].y;
                As[nb][ac[v] + 2][ar[v]] = aReg[v].z;  As[nb][ac[v] + 3][ar[v]] = aReg[v].w;
            }
#pragma unroll
            for (int v = 0; v < W_V4; v++) {
                Ws[nb][wc[v] + 0][wr[v]] = wReg[v].x;  Ws[nb][wc[v] + 1][wr[v]] = wReg[v].y;
                Ws[nb][wc[v] + 2][wr[v]] = wReg[v].z;  Ws[nb][wc[v] + 3][wr[v]] = wReg[v].w;
            }
            __syncthreads();
            buf = nb;
        }
    }

    // ---- LIF epilogue: each thread owns its TMxTN outputs ----
    int myc = 0;
#pragma unroll
    for (int i = 0; i < TM; i++) {
        const int b = bm0 + ty * TM + i;
#pragma unroll
        for (int j = 0; j < TN; j++) {
            const int col = bn0 + tx * TN + j;
            const size_t idx = (size_t)b * H + col;
            float c = acc[i][j] + __ldg(bias + col);
            float m = mem[idx];
            float reset = (m > 1.0f) ? 1.0f : 0.0f;   // spike(m_prev - 1)
            m = beta * m + c - reset;                  // subtract-reset
            float s = (m > 1.0f) ? 1.0f : 0.0f;       // spike(m_new - 1)
            mem[idx] = m;
            if (HAS_SPK) spk[idx] = s;
            if (HAS_SUM) msum[idx] += m;
            myc += (s > 0.f) ? 1 : 0;
        }
    }

    // exact integer spike count: warp reduce -> block reduce -> atomic
#pragma unroll
    for (int o = 16; o > 0; o >>= 1) myc += __shfl_down_sync(0xFFFFFFFFu, myc, o);
    __shared__ int sred[THREADS / 32];
    if ((tid & 31) == 0) sred[tid >> 5] = myc;
    __syncthreads();
    if (tid == 0) {
        int tot = 0;
#pragma unroll
        for (int w = 0; w < THREADS / 32; w++) tot += sred[w];
        atomicAdd(cnt, tot);
    }
}

// ---------------- readout: out = (m3sum/T) @ Wr^T + br ; stats --------------
__global__ void final_kernel(const float* __restrict__ Wr,
                             const float* __restrict__ br,
                             float* __restrict__ out)
{
    const int b = threadIdx.x;   // 256 threads, one batch row each
    float a0 = 0.f, a1 = 0.f;
    for (int j = 0; j < H3; j++) {
        float v = g_m3sum[(size_t)b * H3 + j] / (float)T_STEPS;
        a0 = fmaf(v, Wr[j],      a0);
        a1 = fmaf(v, Wr[H3 + j], a1);
    }
    out[b * 2 + 0] = a0 + br[0];
    out[b * 2 + 1] = a1 + br[1];

    if (b < 3) {
        float denom = (b == 0) ? (float)((double)T_STEPS * BATCH * H1)
                    : (b == 1) ? (float)((double)T_STEPS * BATCH * H2)
                               : (float)((double)T_STEPS * BATCH * H3);
        out[BATCH * 2 + b] = (float)g_cnt[b] / denom;
    }
}

// ---------------- launch ----------------------------------------------------
extern "C" void kernel_launch(void* const* d_in, const int* in_sizes, int n_in,
                              void* d_out, int out_size)
{
    const float* spikes = (const float*)d_in[0];  // [200,256,512]
    const float* W1 = (const float*)d_in[1];      // [1024,512]
    const float* b1 = (const float*)d_in[2];
    const float* W2 = (const float*)d_in[3];      // [1024,1024]
    const float* b2 = (const float*)d_in[4];
    const float* W3 = (const float*)d_in[5];      // [512,1024]
    const float* b3 = (const float*)d_in[6];
    const float* Wr = (const float*)d_in[7];      // [2,512]
    const float* br = (const float*)d_in[8];
    float* out = (float*)d_out;

    float *pm1, *pm2, *pm3, *pms, *ps1, *ps2;
    int* pcnt;
    cudaGetSymbolAddress((void**)&pm1,  g_m1);
    cudaGetSymbolAddress((void**)&pm2,  g_m2);
    cudaGetSymbolAddress((void**)&pm3,  g_m3);
    cudaGetSymbolAddress((void**)&pms,  g_m3sum);
    cudaGetSymbolAddress((void**)&ps1,  g_spk1);
    cudaGetSymbolAddress((void**)&ps2,  g_spk2);
    cudaGetSymbolAddress((void**)&pcnt, g_cnt);

    const float BETA1 = 0.81873075307798182f;  // exp(-1/5)
    const float BETA2 = 0.90483741803595957f;  // exp(-1/10)
    const float BETA3 = 0.95122942450071402f;  // exp(-1/20)

    init_kernel<<<(BATCH * H1 + 255) / 256, 256>>>();

    for (int t = 0; t < T_STEPS; t++) {
        const float* x = spikes + (size_t)t * BATCH * IN_F;
        // L1: [256,512] x [512,1024] -> grid (16, 8)
        layer_kernel<32, 64, 32, 2, 4, IN_F, H1, true,  false>
            <<<dim3(H1 / 64, BATCH / 32), 256>>>(x,   W1, b1, pm1, ps1, nullptr, pcnt + 0, BETA1);
        // L2: [256,1024] x [1024,1024] -> grid (16, 8)
        layer_kernel<32, 64, 32, 2, 4, H1,   H2, true,  false>
            <<<dim3(H2 / 64, BATCH / 32), 256>>>(ps1, W2, b2, pm2, ps2, nullptr, pcnt + 1, BETA2);
        // L3: [256,1024] x [1024,512] -> grid (16, 8)
        layer_kernel<32, 32, 32, 2, 2, H2,   H3, false, true>
            <<<dim3(H3 / 32, BATCH / 32), 256>>>(ps2, W3, b3, pm3, nullptr, pms,  pcnt + 2, BETA3);
    }

    final_kernel<<<1, 256>>>(Wr, br, out);
}

// round 5
// speedup vs baseline: 2.4185x; 1.0413x over previous
#include <cuda_runtime.h>
#include <cuda_bf16.h>
#include <cstdint>

#define T_STEPS 200
#define BATCH   256
#define IN_F    512
#define H1      1024
#define H2      1024
#define H3      512

// ---------------- persistent device state (no allocations allowed) ----------
__device__ float g_m1[BATCH * H1];
__device__ float g_m2[BATCH * H2];
__device__ float g_m3[BATCH * H3];
__device__ float g_m3sum[BATCH * H3];
__device__ int   g_cnt[3];

// bf16 activations (binary spikes -> exact in bf16)
__device__ __nv_bfloat16 g_xb [T_STEPS * BATCH * IN_F];
__device__ __nv_bfloat16 g_s1b[BATCH * H1];
__device__ __nv_bfloat16 g_s2b[BATCH * H2];

// 3-way bf16 weight splits, concatenated along K: Wc[n][3K] = [hi | lo | lolo]
__device__ __nv_bfloat16 g_w1c[H1 * 3 * IN_F];
__device__ __nv_bfloat16 g_w2c[H2 * 3 * H1];
__device__ __nv_bfloat16 g_w3c[H3 * 3 * H2];

// ---------------- prep kernels ----------------------------------------------
__global__ void init_kernel() {
    int idx = blockIdx.x * blockDim.x + threadIdx.x;
    if (idx < BATCH * H1) { g_m1[idx] = 0.f; g_m2[idx] = 0.f; }
    if (idx < BATCH * H3) { g_m3[idx] = 0.f; g_m3sum[idx] = 0.f; }
    if (idx < 3) g_cnt[idx] = 0;
}

__global__ void cvt_x_kernel(const float* __restrict__ src, int n4) {
    int i = blockIdx.x * blockDim.x + threadIdx.x;
    if (i < n4) {
        float4 v = ((const float4*)src)[i];
        __nv_bfloat162* d = (__nv_bfloat162*)g_xb;
        d[2 * i + 0] = __floats2bfloat162_rn(v.x, v.y);
        d[2 * i + 1] = __floats2bfloat162_rn(v.z, v.w);
    }
}

// split fp32 weight into hi+lo+lolo bf16; write into K-concatenated layout
__global__ void prep_w_kernel(const float* __restrict__ src, int n, int K,
                              __nv_bfloat16* __restrict__ dst) {
    int i = blockIdx.x * blockDim.x + threadIdx.x;
    if (i < n) {
        int row = i / K, k = i % K;
        float w  = src[i];
        __nv_bfloat16 h = __float2bfloat16(w);
        float r1 = w - __bfloat162float(h);
        __nv_bfloat16 l = __float2bfloat16(r1);
        float r2 = r1 - __bfloat162float(l);
        size_t base = (size_t)row * (3 * K) + k;
        dst[base]         = h;
        dst[base + K]     = l;
        dst[base + 2 * K] = __float2bfloat16(r2);
    }
}

// ---------------- fused bf16 mma.sync GEMM + LIF layer ----------------------
// C[m,n] = sum_{k'} A[m, k' mod K] * Wc[n, k'] + bias[n]; then LIF update.
// BM=32 fixed. BN in {32, 64}. 128 threads = 4 warps, warps split N.
template<int K, int BN, int H, bool HAS_SPK, bool HAS_SUM>
__global__ void __launch_bounds__(128)
layer_mma(const __nv_bfloat16* __restrict__ A,
          const __nv_bfloat16* __restrict__ Wc,
          const float* __restrict__ bias,
          float* __restrict__ mem,
          __nv_bfloat16* __restrict__ spk,
          float* __restrict__ msum,
          int*  __restrict__ cnt,
          float beta)
{
    constexpr int BM = 32;
    constexpr int BK = 64;                    // bf16 elements per K-chunk
    constexpr int K3 = 3 * K;
    constexpr int NITER = K3 / BK;
    constexpr int NF = BN / 32;               // n8-frags per warp (1 or 2)
    constexpr int RS = 36;                    // smem row stride in u32 (72 bf16)
    constexpr int A_IT = (BM * 8) / 128;      // uint4 per thread for A tile (2)
    constexpr int W_IT = (BN * 8) / 128;      // uint4 per thread for W tile (2/4)

    __shared__ __align__(16) uint32_t As[2][BM * RS];
    __shared__ __align__(16) uint32_t Ws[2][BN * RS];
    __shared__ int s_red[4];

    const int tid = threadIdx.x;
    const int wid = tid >> 5;
    const int lane = tid & 31;
    const int q  = lane & 3;        // quad index
    const int l8 = lane >> 2;       // 0..7
    const int bn0 = blockIdx.x * BN;
    const int bm0 = blockIdx.y * BM;
    const int woff = wid * (BN / 4);      // warp's n offset inside CTA tile

    // staging indices (uint4 granularity: 8 bf16 per load)
    const int sr = tid >> 3;        // 0..15
    const int sg = tid & 7;         // 0..7

    float acc[2][NF][4];
#pragma unroll
    for (int mf = 0; mf < 2; mf++)
#pragma unroll
        for (int nf = 0; nf < NF; nf++)
#pragma unroll
            for (int e = 0; e < 4; e++) acc[mf][nf][e] = 0.f;

    uint4 aR[A_IT], wR[W_IT];

    // ---- prologue: chunk 0 -> buffer 0 ----
#pragma unroll
    for (int u = 0; u < A_IT; u++) {
        int r = sr + u * 16;
        aR[u] = *(const uint4*)(A + (size_t)(bm0 + r) * K + sg * 8);
    }
#pragma unroll
    for (int u = 0; u < W_IT; u++) {
        int r = sr + u * 16;
        wR[u] = *(const uint4*)(Wc + (size_t)(bn0 + r) * K3 + sg * 8);
    }
#pragma unroll
    for (int u = 0; u < A_IT; u++)
        *(uint4*)&As[0][(sr + u * 16) * RS + sg * 4] = aR[u];
#pragma unroll
    for (int u = 0; u < W_IT; u++)
        *(uint4*)&Ws[0][(sr + u * 16) * RS + sg * 4] = wR[u];
    __syncthreads();

    int buf = 0;
    for (int c = 0; c < NITER; c++) {
        // prefetch chunk c+1 into registers
        if (c + 1 < NITER) {
            const int ak0 = ((c + 1) * BK) % K;
            const int wk0 = (c + 1) * BK;
#pragma unroll
            for (int u = 0; u < A_IT; u++) {
                int r = sr + u * 16;
                aR[u] = *(const uint4*)(A + (size_t)(bm0 + r) * K + ak0 + sg * 8);
            }
#pragma unroll
            for (int u = 0; u < W_IT; u++) {
                int r = sr + u * 16;
                wR[u] = *(const uint4*)(Wc + (size_t)(bn0 + r) * K3 + wk0 + sg * 8);
            }
        }

        // compute 4 k16-steps on current buffer
        const uint32_t* __restrict__ Ab = As[buf];
        const uint32_t* __restrict__ Wb = Ws[buf];
#pragma unroll
        for (int kk = 0; kk < 4; kk++) {
            const int ko = kk * 8 + q;
            uint32_t a[2][4];
#pragma unroll
            for (int mf = 0; mf < 2; mf++) {
                const int r0 = (mf * 16 + l8) * RS;
                const int r1 = (mf * 16 + 8 + l8) * RS;
                a[mf][0] = Ab[r0 + ko];
                a[mf][1] = Ab[r1 + ko];
                a[mf][2] = Ab[r0 + ko + 4];
                a[mf][3] = Ab[r1 + ko + 4];
            }
            uint32_t b[NF][2];
#pragma unroll
            for (int nf = 0; nf < NF; nf++) {
                const int nr = (woff + nf * 8 + l8) * RS;
                b[nf][0] = Wb[nr + ko];
                b[nf][1] = Wb[nr + ko + 4];
            }
#pragma unroll
            for (int mf = 0; mf < 2; mf++)
#pragma unroll
                for (int nf = 0; nf < NF; nf++) {
                    asm volatile(
                        "mma.sync.aligned.m16n8k16.row.col.f32.bf16.bf16.f32 "
                        "{%0,%1,%2,%3}, {%4,%5,%6,%7}, {%8,%9}, {%0,%1,%2,%3};"
                        : "+f"(acc[mf][nf][0]), "+f"(acc[mf][nf][1]),
                          "+f"(acc[mf][nf][2]), "+f"(acc[mf][nf][3])
                        : "r"(a[mf][0]), "r"(a[mf][1]), "r"(a[mf][2]), "r"(a[mf][3]),
                          "r"(b[nf][0]), "r"(b[nf][1]));
                }
        }

        // store prefetched chunk into other buffer
        if (c + 1 < NITER) {
            const int nb = buf ^ 1;
#pragma unroll
            for (int u = 0; u < A_IT; u++)
                *(uint4*)&As[nb][(sr + u * 16) * RS + sg * 4] = aR[u];
#pragma unroll
            for (int u = 0; u < W_IT; u++)
                *(uint4*)&Ws[nb][(sr + u * 16) * RS + sg * 4] = wR[u];
            __syncthreads();
            buf = nb;
        }
    }

    // ---- LIF epilogue: thread owns 2 cols x (2 rows x 2 mf x NF) ----
    int myc = 0;
#pragma unroll
    for (int mf = 0; mf < 2; mf++) {
#pragma unroll
        for (int half = 0; half < 2; half++) {
            const int m = bm0 + mf * 16 + half * 8 + l8;
#pragma unroll
            for (int nf = 0; nf < NF; nf++) {
                const int ncol = bn0 + woff + nf * 8 + q * 2;
                const size_t idx = (size_t)m * H + ncol;
                float2 cc = make_float2(acc[mf][nf][half * 2], acc[mf][nf][half * 2 + 1]);
                float2 bs = *reinterpret_cast<const float2*>(bias + ncol);
                float2 mm = *reinterpret_cast<const float2*>(mem + idx);
                float c0 = cc.x + bs.x, c1 = cc.y + bs.y;
                float r0 = (mm.x > 1.0f) ? 1.0f : 0.0f;
                float r1 = (mm.y > 1.0f) ? 1.0f : 0.0f;
                mm.x = beta * mm.x + c0 - r0;
                mm.y = beta * mm.y + c1 - r1;
                float s0 = (mm.x > 1.0f) ? 1.0f : 0.0f;
                float s1 = (mm.y > 1.0f) ? 1.0f : 0.0f;
                *reinterpret_cast<float2*>(mem + idx) = mm;
                if (HAS_SUM) {
                    float2 su = *reinterpret_cast<const float2*>(msum + idx);
                    su.x += mm.x; su.y += mm.y;
                    *reinterpret_cast<float2*>(msum + idx) = su;
                }
                if (HAS_SPK) {
                    *reinterpret_cast<__nv_bfloat162*>(spk + idx) =
                        __floats2bfloat162_rn(s0, s1);
                }
                myc += (int)s0 + (int)s1;
            }
        }
    }

    // exact spike count
#pragma unroll
    for (int o = 16; o > 0; o >>= 1) myc += __shfl_down_sync(0xFFFFFFFFu, myc, o);
    if ((tid & 31) == 0) s_red[wid] = myc;
    __syncthreads();
    if (tid == 0) atomicAdd(cnt, s_red[0] + s_red[1] + s_red[2] + s_red[3]);
}

// ---------------- readout ----------------------------------------------------
__global__ void final_kernel(const float* __restrict__ Wr,
                             const float* __restrict__ br,
                             float* __restrict__ out)
{
    const int b = threadIdx.x;
    float a0 = 0.f, a1 = 0.f;
    for (int j = 0; j < H3; j++) {
        float v = g_m3sum[(size_t)b * H3 + j] / (float)T_STEPS;
        a0 = fmaf(v, Wr[j],      a0);
        a1 = fmaf(v, Wr[H3 + j], a1);
    }
    out[b * 2 + 0] = a0 + br[0];
    out[b * 2 + 1] = a1 + br[1];
    if (b < 3) {
        float denom = (b == 0) ? (float)((double)T_STEPS * BATCH * H1)
                    : (b == 1) ? (float)((double)T_STEPS * BATCH * H2)
                               : (float)((double)T_STEPS * BATCH * H3);
        out[BATCH * 2 + b] = (float)g_cnt[b] / denom;
    }
}

// ---------------- launch ----------------------------------------------------
extern "C" void kernel_launch(void* const* d_in, const int* in_sizes, int n_in,
                              void* d_out, int out_size)
{
    const float* spikes = (const float*)d_in[0];
    const float* W1 = (const float*)d_in[1];
    const float* b1 = (const float*)d_in[2];
    const float* W2 = (const float*)d_in[3];
    const float* b2 = (const float*)d_in[4];
    const float* W3 = (const float*)d_in[5];
    const float* b3 = (const float*)d_in[6];
    const float* Wr = (const float*)d_in[7];
    const float* br = (const float*)d_in[8];
    float* out = (float*)d_out;

    float *pm1, *pm2, *pm3, *pms;
    __nv_bfloat16 *pxb, *ps1, *ps2, *w1c, *w2c, *w3c;
    int* pcnt;
    cudaGetSymbolAddress((void**)&pm1, g_m1);
    cudaGetSymbolAddress((void**)&pm2, g_m2);
    cudaGetSymbolAddress((void**)&pm3, g_m3);
    cudaGetSymbolAddress((void**)&pms, g_m3sum);
    cudaGetSymbolAddress((void**)&pxb, g_xb);
    cudaGetSymbolAddress((void**)&ps1, g_s1b);
    cudaGetSymbolAddress((void**)&ps2, g_s2b);
    cudaGetSymbolAddress((void**)&w1c, g_w1c);
    cudaGetSymbolAddress((void**)&w2c, g_w2c);
    cudaGetSymbolAddress((void**)&w3c, g_w3c);
    cudaGetSymbolAddress((void**)&pcnt, g_cnt);

    const float BETA1 = 0.81873075307798182f;  // exp(-1/5)
    const float BETA2 = 0.90483741803595957f;  // exp(-1/10)
    const float BETA3 = 0.95122942450071402f;  // exp(-1/20)

    init_kernel<<<(BATCH * H1 + 255) / 256, 256>>>();
    {
        int n4 = T_STEPS * BATCH * IN_F / 4;
        cvt_x_kernel<<<(n4 + 255) / 256, 256>>>(spikes, n4);
        prep_w_kernel<<<(H1 * IN_F + 255) / 256, 256>>>(W1, H1 * IN_F, IN_F, w1c);
        prep_w_kernel<<<(H2 * H1   + 255) / 256, 256>>>(W2, H2 * H1,   H1,   w2c);
        prep_w_kernel<<<(H3 * H2   + 255) / 256, 256>>>(W3, H3 * H2,   H2,   w3c);
    }

    for (int t = 0; t < T_STEPS; t++) {
        const __nv_bfloat16* x = pxb + (size_t)t * BATCH * IN_F;
        // L1: [256,512] @ Wc1[1024, 1536] -> grid (1024/64, 256/32) = (16, 8)
        layer_mma<IN_F, 64, H1, true,  false><<<dim3(H1 / 64, BATCH / 32), 128>>>(
            x,   w1c, b1, pm1, ps1, nullptr, pcnt + 0, BETA1);
        // L2: [256,1024] @ Wc2[1024, 3072] -> grid (16, 8)
        layer_mma<H1,   64, H2, true,  false><<<dim3(H2 / 64, BATCH / 32), 128>>>(
            ps1, w2c, b2, pm2, ps2, nullptr, pcnt + 1, BETA2);
        // L3: [256,1024] @ Wc3[512, 3072] -> grid (512/32, 256/32) = (16, 8)
        layer_mma<H2,   32, H3, false, true ><<<dim3(H3 / 32, BATCH / 32), 128>>>(
            ps2, w3c, b3, pm3, nullptr, pms, pcnt + 2, BETA3);
    }

    final_kernel<<<1, 256>>>(Wr, br, out);
}

// round 6
// speedup vs baseline: 8.1027x; 3.3503x over previous
#include <cuda_runtime.h>
#include <cstdint>

#define T_STEPS 200
#define BATCH   256
#define IN_F    512
#define H1      1024
#define H2      1024
#define H3      512
#define NCTA    128
#define PAD     12

// ---------------- persistent device state (no allocations allowed) ----------
__device__ float g_m3sum[BATCH * H3];
__device__ int   g_cnt[3];
__device__ unsigned g_xbits[T_STEPS * BATCH * (IN_F / 32)];
__device__ unsigned char g_bits1[2][BATCH * 128];
__device__ unsigned char g_bits2[2][BATCH * 128];
__device__ volatile int g_arrive[NCTA];
__device__ volatile int g_release;

// ---------------- prep kernels ----------------------------------------------
__global__ void init_kernel() {
    int i = blockIdx.x * blockDim.x + threadIdx.x;
    if (i < 3) g_cnt[i] = 0;
    if (i < NCTA) g_arrive[i] = 0;
    if (i == 0) g_release = 0;
}

// pack input spikes (fp32 0/1) into bitmask words, row-major [t][r][16]
__global__ void build_xbits(const float* __restrict__ s) {
    int j = blockIdx.x * blockDim.x + threadIdx.x;
    if (j < T_STEPS * BATCH * (IN_F / 32)) {
        const float4* p = (const float4*)(s + (size_t)j * 32);
        unsigned b = 0;
#pragma unroll
        for (int q = 0; q < 8; q++) {
            float4 v = p[q];
            b |= (v.x > 0.5f ? 1u : 0u) << (4 * q + 0);
            b |= (v.y > 0.5f ? 1u : 0u) << (4 * q + 1);
            b |= (v.z > 0.5f ? 1u : 0u) << (4 * q + 2);
            b |= (v.w > 0.5f ? 1u : 0u) << (4 * q + 3);
        }
        g_xbits[j] = b;
    }
}

// ---------------- global barrier (no atomics; all CTAs resident) ------------
__device__ __forceinline__ void gbar(int gen, int cta, int tid) {
    __syncthreads();
    if (tid == 0) { __threadfence(); g_arrive[cta] = gen; }
    if (cta == 0 && tid < 32) {
        for (;;) {
            int v0 = g_arrive[tid];
            int v1 = g_arrive[tid + 32];
            int v2 = g_arrive[tid + 64];
            int v3 = g_arrive[tid + 96];
            if (__all_sync(0xFFFFFFFFu,
                           v0 >= gen && v1 >= gen && v2 >= gen && v3 >= gen))
                break;
        }
        if (tid == 0) { __threadfence(); g_release = gen; }
    }
    if (tid == 0) {
        while (g_release < gen) __nanosleep(32);
        __threadfence();
    }
    __syncthreads();
}

// ---------------- copy bitmask global -> padded SMEM ------------------------
template<int KW>
__device__ __forceinline__ void copy_bits(const unsigned* __restrict__ src,
                                          unsigned* dst, int tid) {
#pragma unroll
    for (int u = 0; u < KW; u++) {
        int i = tid + u * 256;
        int rr = i / KW, w = i % KW;
        dst[rr * (KW + 1) + w] = __ldcg(src + i);
    }
}

// ---------------- sparse accumulate + LIF for one row -----------------------
template<int KW, int NC, bool HAS_SUM>
__device__ __forceinline__ unsigned lif_row(const unsigned* __restrict__ sbits,
                                            int r,
                                            const float* __restrict__ Wsm,
                                            const float* __restrict__ br,
                                            float beta,
                                            float* m, float* msum, int& cnt) {
    float acc[NC];
#pragma unroll
    for (int j = 0; j < NC; j++) acc[j] = br[j];
    const unsigned* rb = sbits + r * (KW + 1);
    for (int w = 0; w < KW; w++) {
        unsigned bits = rb[w];
        while (bits) {
            int b = __ffs(bits) - 1;
            bits &= bits - 1;
            const float4* wp = (const float4*)(Wsm + (size_t)(w * 32 + b) * PAD);
            float4 v0 = wp[0];
            acc[0] += v0.x; acc[1] += v0.y; acc[2] += v0.z; acc[3] += v0.w;
            if (NC == 8) {
                float4 v1 = wp[1];
                acc[4] += v1.x; acc[5] += v1.y; acc[6] += v1.z; acc[7] += v1.w;
            }
        }
    }
    unsigned byte = 0;
#pragma unroll
    for (int j = 0; j < NC; j++) {
        float mm = m[j];
        float reset = (mm > 1.0f) ? 1.0f : 0.0f;   // spike(m_prev - 1)
        mm = beta * mm + acc[j] - reset;           // subtract-reset
        unsigned sp = (mm > 1.0f) ? 1u : 0u;       // spike(m_new - 1)
        m[j] = mm;
        if (HAS_SUM) msum[j] += mm;
        byte |= sp << j;
    }
    cnt += __popc(byte);
    return byte;
}

// ---------------- THE persistent kernel --------------------------------------
__global__ void __launch_bounds__(256, 1)
snn_persistent(const float* __restrict__ W1, const float* __restrict__ b1,
               const float* __restrict__ W2, const float* __restrict__ b2,
               const float* __restrict__ W3, const float* __restrict__ b3)
{
    extern __shared__ float smem[];
    float* W1s = smem;                     // [512][12]
    float* W2s = W1s + IN_F * PAD;         // [1024][12]
    float* W3s = W2s + H1 * PAD;           // [1024][12]
    unsigned* sbits = (unsigned*)(W3s + H2 * PAD);  // up to [256][33]

    const int tid = threadIdx.x;
    const int cta = blockIdx.x;
    const int wid = tid >> 5, lane = tid & 31;

    // ---- preload weight slices (transposed: Wsm[k][col]) ----
    for (int i = tid; i < 8 * IN_F; i += 256) {
        int n = i / IN_F, k = i % IN_F;
        W1s[k * PAD + n] = W1[(size_t)(8 * cta + n) * IN_F + k];
    }
    for (int i = tid; i < 8 * H1; i += 256) {
        int n = i / H1, k = i % H1;
        W2s[k * PAD + n] = W2[(size_t)(8 * cta + n) * H1 + k];
    }
    for (int i = tid; i < 4 * H2; i += 256) {
        int n = i / H2, k = i % H2;
        W3s[k * PAD + n] = W3[(size_t)(4 * cta + n) * H2 + k];
    }
    float b1r[8], b2r[8], b3r[4];
#pragma unroll
    for (int j = 0; j < 8; j++) { b1r[j] = b1[8 * cta + j]; b2r[j] = b2[8 * cta + j]; }
#pragma unroll
    for (int j = 0; j < 4; j++) b3r[j] = b3[4 * cta + j];

    float m1[8] = {0}, m2[8] = {0}, m3[4] = {0}, ms[4] = {0};
    int c1 = 0, c2 = 0, c3 = 0;
    __syncthreads();

    const float BETA1 = 0.81873075307798182f;  // exp(-1/5)
    const float BETA2 = 0.90483741803595957f;  // exp(-1/10)
    const float BETA3 = 0.95122942450071402f;  // exp(-1/20)

    int gen = 1;
    for (int t = 0; t < T_STEPS; t++) {
        // ---- layer 1 ----
        copy_bits<16>(g_xbits + (size_t)t * BATCH * 16, sbits, tid);
        __syncthreads();
        unsigned by = lif_row<16, 8, false>(sbits, tid, W1s, b1r, BETA1, m1, nullptr, c1);
        g_bits1[t & 1][tid * 128 + cta] = (unsigned char)by;
        gbar(gen, cta, tid); gen++;

        // ---- layer 2 ----
        copy_bits<32>((const unsigned*)g_bits1[t & 1], sbits, tid);
        __syncthreads();
        by = lif_row<32, 8, false>(sbits, tid, W2s, b2r, BETA2, m2, nullptr, c2);
        g_bits2[t & 1][tid * 128 + cta] = (unsigned char)by;
        gbar(gen, cta, tid); gen++;

        // ---- layer 3 ----
        copy_bits<32>((const unsigned*)g_bits2[t & 1], sbits, tid);
        __syncthreads();
        (void)lif_row<32, 4, true>(sbits, tid, W3s, b3r, BETA3, m3, ms, c3);
        __syncthreads();   // all reads of sbits done before next step overwrites
    }

    // ---- write m3sum slice (row tid, cols 4c..4c+3) ----
    *(float4*)(g_m3sum + (size_t)tid * H3 + 4 * cta) =
        make_float4(ms[0], ms[1], ms[2], ms[3]);

    // ---- exact spike counts: warp reduce -> block -> atomic ----
#pragma unroll
    for (int o = 16; o > 0; o >>= 1) {
        c1 += __shfl_down_sync(0xFFFFFFFFu, c1, o);
        c2 += __shfl_down_sync(0xFFFFFFFFu, c2, o);
        c3 += __shfl_down_sync(0xFFFFFFFFu, c3, o);
    }
    __shared__ int sr_[3][8];
    if (lane == 0) { sr_[0][wid] = c1; sr_[1][wid] = c2; sr_[2][wid] = c3; }
    __syncthreads();
    if (tid < 3) {
        int s = 0;
#pragma unroll
        for (int w = 0; w < 8; w++) s += sr_[tid][w];
        atomicAdd(&g_cnt[tid], s);
    }
}

// ---------------- readout ----------------------------------------------------
__global__ void final_kernel(const float* __restrict__ Wr,
                             const float* __restrict__ br,
                             float* __restrict__ out)
{
    const int b = threadIdx.x;
    float a0 = 0.f, a1 = 0.f;
    for (int j = 0; j < H3; j++) {
        float v = g_m3sum[(size_t)b * H3 + j] / (float)T_STEPS;
        a0 = fmaf(v, Wr[j],      a0);
        a1 = fmaf(v, Wr[H3 + j], a1);
    }
    out[b * 2 + 0] = a0 + br[0];
    out[b * 2 + 1] = a1 + br[1];
    if (b < 3) {
        float denom = (b == 0) ? (float)((double)T_STEPS * BATCH * H1)
                    : (b == 1) ? (float)((double)T_STEPS * BATCH * H2)
                               : (float)((double)T_STEPS * BATCH * H3);
        out[BATCH * 2 + b] = (float)g_cnt[b] / denom;
    }
}

// ---------------- launch ----------------------------------------------------
extern "C" void kernel_launch(void* const* d_in, const int* in_sizes, int n_in,
                              void* d_out, int out_size)
{
    const float* spikes = (const float*)d_in[0];
    const float* W1 = (const float*)d_in[1];
    const float* b1 = (const float*)d_in[2];
    const float* W2 = (const float*)d_in[3];
    const float* b2 = (const float*)d_in[4];
    const float* W3 = (const float*)d_in[5];
    const float* b3 = (const float*)d_in[6];
    const float* Wr = (const float*)d_in[7];
    const float* br = (const float*)d_in[8];
    float* out = (float*)d_out;

    const int DSMEM = (IN_F + H1 + H2) * PAD * 4 + BATCH * 33 * 4;  // 156,672 B
    cudaFuncSetAttribute(snn_persistent,
                         cudaFuncAttributeMaxDynamicSharedMemorySize, DSMEM);

    init_kernel<<<1, 256>>>();
    {
        int n = T_STEPS * BATCH * (IN_F / 32);
        build_xbits<<<(n + 255) / 256, 256>>>(spikes);
    }
    snn_persistent<<<NCTA, 256, DSMEM>>>(W1, b1, W2, b2, W3, b3);
    final_kernel<<<1, 256>>>(Wr, br, out);
}

// round 7
// speedup vs baseline: 13.5792x; 1.6759x over previous
#include <cuda_runtime.h>
#include <cstdint>

#define T_STEPS 200
#define BATCH   256
#define IN_F    512
#define H1      1024
#define H2      1024
#define H3      512
#define NCTA    128
#define PAD     12

// ---------------- persistent device state (no allocations allowed) ----------
__device__ float g_m3sum[BATCH * H3];
__device__ int   g_cnt[3];
__device__ unsigned g_xbits[T_STEPS * BATCH * (IN_F / 32)];
__device__ unsigned char g_bits1[T_STEPS][BATCH * 128];   // spk1 history (6.5MB)
__device__ unsigned char g_bits2[T_STEPS][BATCH * 128];   // spk2 history (6.5MB)
__device__ volatile int g_arrive[NCTA];
__device__ volatile int g_release;

// ---------------- prep kernels ----------------------------------------------
__global__ void init_kernel() {
    int i = blockIdx.x * blockDim.x + threadIdx.x;
    if (i < 3) g_cnt[i] = 0;
    if (i < NCTA) g_arrive[i] = 0;
    if (i == 0) g_release = 0;
}

// pack input spikes (fp32 0/1) into bitmask words, row-major [t][r][16]
__global__ void build_xbits(const float* __restrict__ s) {
    int j = blockIdx.x * blockDim.x + threadIdx.x;
    if (j < T_STEPS * BATCH * (IN_F / 32)) {
        const float4* p = (const float4*)(s + (size_t)j * 32);
        unsigned b = 0;
#pragma unroll
        for (int q = 0; q < 8; q++) {
            float4 v = p[q];
            b |= (v.x > 0.5f ? 1u : 0u) << (4 * q + 0);
            b |= (v.y > 0.5f ? 1u : 0u) << (4 * q + 1);
            b |= (v.z > 0.5f ? 1u : 0u) << (4 * q + 2);
            b |= (v.w > 0.5f ? 1u : 0u) << (4 * q + 3);
        }
        g_xbits[j] = b;
    }
}

// ---------------- global barrier (2 uses total now) --------------------------
__device__ __forceinline__ void gbar(int gen, int cta, int tid) {
    __syncthreads();
    if (tid == 0) { __threadfence(); g_arrive[cta] = gen; }
    if (cta == 0 && tid < 32) {
        for (;;) {
            int v0 = g_arrive[tid];
            int v1 = g_arrive[tid + 32];
            int v2 = g_arrive[tid + 64];
            int v3 = g_arrive[tid + 96];
            if (__all_sync(0xFFFFFFFFu,
                           v0 >= gen && v1 >= gen && v2 >= gen && v3 >= gen))
                break;
        }
        if (tid == 0) { __threadfence(); g_release = gen; }
    }
    if (tid == 0) {
        while (g_release < gen) { }
        __threadfence();
    }
    __syncthreads();
}

// ---------------- one layer, all 200 steps (register-prefetch pipeline) ------
// srcbits: [T][BATCH*KW] words. dstbits (if HAS_SPK): [T][BATCH*128] bytes.
template<int KW, int NC, bool HAS_SPK, bool HAS_SUM>
__device__ __forceinline__ void phase_loop(const unsigned* __restrict__ srcbits,
                                           unsigned char* __restrict__ dstbits,
                                           const float* __restrict__ Wsm,
                                           const float* __restrict__ br,
                                           float beta,
                                           unsigned* __restrict__ sbits,
                                           int cta, int tid,
                                           float* m, float* msum, int& cnt)
{
    constexpr int V = (BATCH * KW) / (256 * 4);   // uint4 per thread
    uint4 regs[V];

    // prefetch t = 0
#pragma unroll
    for (int v = 0; v < V; v++)
        regs[v] = __ldcg(&((const uint4*)srcbits)[tid + v * 256]);

    for (int t = 0; t < T_STEPS; t++) {
        // store prefetched bits into padded smem
#pragma unroll
        for (int v = 0; v < V; v++) {
            int idx = (tid + v * 256) * 4;
            int r = idx / KW, c = idx % KW;
            unsigned* p = &sbits[r * (KW + 1) + c];
            p[0] = regs[v].x; p[1] = regs[v].y; p[2] = regs[v].z; p[3] = regs[v].w;
        }
        __syncthreads();

        // prefetch t+1 (overlaps compute)
        if (t + 1 < T_STEPS) {
            const uint4* sp = (const uint4*)(srcbits + (size_t)(t + 1) * BATCH * KW);
#pragma unroll
            for (int v = 0; v < V; v++)
                regs[v] = __ldcg(&sp[tid + v * 256]);
        }

        // sparse accumulate for this thread's row
        float acc[NC];
#pragma unroll
        for (int j = 0; j < NC; j++) acc[j] = br[j];
        const unsigned* rb = sbits + tid * (KW + 1);
#pragma unroll 4
        for (int w = 0; w < KW; w++) {
            unsigned bits = rb[w];
            while (bits) {
                int b = __ffs(bits) - 1;
                bits &= bits - 1;
                const float4* wp = (const float4*)(Wsm + (size_t)(w * 32 + b) * PAD);
                float4 v0 = wp[0];
                acc[0] += v0.x; acc[1] += v0.y; acc[2] += v0.z; acc[3] += v0.w;
                if (NC == 8) {
                    float4 v1 = wp[1];
                    acc[4] += v1.x; acc[5] += v1.y; acc[6] += v1.z; acc[7] += v1.w;
                }
            }
        }

        // LIF update
        unsigned byte = 0;
#pragma unroll
        for (int j = 0; j < NC; j++) {
            float mm = m[j];
            float reset = (mm > 1.0f) ? 1.0f : 0.0f;   // spike(m_prev - 1)
            mm = beta * mm + acc[j] - reset;           // subtract-reset
            unsigned sp = (mm > 1.0f) ? 1u : 0u;       // spike(m_new - 1)
            m[j] = mm;
            if (HAS_SUM) msum[j] += mm;
            byte |= sp << j;
        }
        cnt += __popc(byte);
        if (HAS_SPK)
            dstbits[(size_t)t * (BATCH * 128) + tid * 128 + cta] = (unsigned char)byte;

        __syncthreads();   // all sbits reads done before next store
    }
}

// ---------------- THE persistent kernel: 3 phases, 2 barriers ----------------
__global__ void __launch_bounds__(256, 1)
snn_phased(const float* __restrict__ W1, const float* __restrict__ b1,
           const float* __restrict__ W2, const float* __restrict__ b2,
           const float* __restrict__ W3, const float* __restrict__ b3)
{
    extern __shared__ float smem[];
    float* Wsm = smem;                                 // up to [1024][12]
    unsigned* sbits = (unsigned*)(Wsm + 1024 * PAD);   // up to [256][33]

    const int tid = threadIdx.x;
    const int cta = blockIdx.x;
    const int wid = tid >> 5, lane = tid & 31;

    const float BETA1 = 0.81873075307798182f;  // exp(-1/5)
    const float BETA2 = 0.90483741803595957f;  // exp(-1/10)
    const float BETA3 = 0.95122942450071402f;  // exp(-1/20)

    int c1 = 0, c2 = 0, c3 = 0;

    // ================= phase 1: layer 1, all steps =================
    {
        for (int i = tid; i < 8 * IN_F; i += 256) {
            int n = i / IN_F, k = i % IN_F;
            Wsm[k * PAD + n] = W1[(size_t)(8 * cta + n) * IN_F + k];
        }
        float b1r[8];
#pragma unroll
        for (int j = 0; j < 8; j++) b1r[j] = b1[8 * cta + j];
        float m1[8] = {0};
        __syncthreads();
        phase_loop<16, 8, true, false>(g_xbits, &g_bits1[0][0], Wsm, b1r, BETA1,
                                       sbits, cta, tid, m1, nullptr, c1);
    }
    gbar(1, cta, tid);

    // ================= phase 2: layer 2, all steps =================
    {
        for (int i = tid; i < 8 * H1; i += 256) {
            int n = i / H1, k = i % H1;
            Wsm[k * PAD + n] = W2[(size_t)(8 * cta + n) * H1 + k];
        }
        float b2r[8];
#pragma unroll
        for (int j = 0; j < 8; j++) b2r[j] = b2[8 * cta + j];
        float m2[8] = {0};
        __syncthreads();
        phase_loop<32, 8, true, false>((const unsigned*)&g_bits1[0][0], &g_bits2[0][0],
                                       Wsm, b2r, BETA2, sbits, cta, tid, m2, nullptr, c2);
    }
    gbar(2, cta, tid);

    // ================= phase 3: layer 3, all steps =================
    {
        for (int i = tid; i < 4 * H2; i += 256) {
            int n = i / H2, k = i % H2;
            Wsm[k * PAD + n] = W3[(size_t)(4 * cta + n) * H2 + k];
        }
        float b3r[4];
#pragma unroll
        for (int j = 0; j < 4; j++) b3r[j] = b3[4 * cta + j];
        float m3[4] = {0}, ms[4] = {0};
        __syncthreads();
        phase_loop<32, 4, false, true>((const unsigned*)&g_bits2[0][0], nullptr,
                                       Wsm, b3r, BETA3, sbits, cta, tid, m3, ms, c3);

        // write m3sum slice (row tid, cols 4c..4c+3)
        *(float4*)(g_m3sum + (size_t)tid * H3 + 4 * cta) =
            make_float4(ms[0], ms[1], ms[2], ms[3]);
    }

    // ---- exact spike counts ----
#pragma unroll
    for (int o = 16; o > 0; o >>= 1) {
        c1 += __shfl_down_sync(0xFFFFFFFFu, c1, o);
        c2 += __shfl_down_sync(0xFFFFFFFFu, c2, o);
        c3 += __shfl_down_sync(0xFFFFFFFFu, c3, o);
    }
    __shared__ int sr_[3][8];
    if (lane == 0) { sr_[0][wid] = c1; sr_[1][wid] = c2; sr_[2][wid] = c3; }
    __syncthreads();
    if (tid < 3) {
        int s = 0;
#pragma unroll
        for (int w = 0; w < 8; w++) s += sr_[tid][w];
        atomicAdd(&g_cnt[tid], s);
    }
}

// ---------------- readout (parallel: block per batch row) --------------------
__global__ void final_kernel(const float* __restrict__ Wr,
                             const float* __restrict__ br,
                             float* __restrict__ out)
{
    const int b = blockIdx.x;
    const int t = threadIdx.x;
    float a0 = 0.f, a1 = 0.f;
    for (int j = t; j < H3; j += 128) {
        float v = g_m3sum[(size_t)b * H3 + j] / (float)T_STEPS;
        a0 = fmaf(v, Wr[j],      a0);
        a1 = fmaf(v, Wr[H3 + j], a1);
    }
    __shared__ float s0[128], s1[128];
    s0[t] = a0; s1[t] = a1;
    __syncthreads();
    for (int o = 64; o > 0; o >>= 1) {
        if (t < o) { s0[t] += s0[t + o]; s1[t] += s1[t + o]; }
        __syncthreads();
    }
    if (t == 0) {
        out[b * 2 + 0] = s0[0] + br[0];
        out[b * 2 + 1] = s1[0] + br[1];
    }
    if (b == 0 && t < 3) {
        float denom = (t == 0) ? (float)((double)T_STEPS * BATCH * H1)
                    : (t == 1) ? (float)((double)T_STEPS * BATCH * H2)
                               : (float)((double)T_STEPS * BATCH * H3);
        out[BATCH * 2 + t] = (float)g_cnt[t] / denom;
    }
}

// ---------------- launch ----------------------------------------------------
extern "C" void kernel_launch(void* const* d_in, const int* in_sizes, int n_in,
                              void* d_out, int out_size)
{
    const float* spikes = (const float*)d_in[0];
    const float* W1 = (const float*)d_in[1];
    const float* b1 = (const float*)d_in[2];
    const float* W2 = (const float*)d_in[3];
    const float* b2 = (const float*)d_in[4];
    const float* W3 = (const float*)d_in[5];
    const float* b3 = (const float*)d_in[6];
    const float* Wr = (const float*)d_in[7];
    const float* br = (const float*)d_in[8];
    float* out = (float*)d_out;

    const int DSMEM = 1024 * PAD * 4 + BATCH * 33 * 4;   // 49152 + 33792 = 82,944 B
    cudaFuncSetAttribute(snn_phased,
                         cudaFuncAttributeMaxDynamicSharedMemorySize, DSMEM);

    init_kernel<<<1, 256>>>();
    {
        int n = T_STEPS * BATCH * (IN_F / 32);
        build_xbits<<<(n + 255) / 256, 256>>>(spikes);
    }
    snn_phased<<<NCTA, 256, DSMEM>>>(W1, b1, W2, b2, W3, b3);
    final_kernel<<<BATCH, 128>>>(Wr, br, out);
}

// round 8
// speedup vs baseline: 14.3134x; 1.0541x over previous
#include <cuda_runtime.h>
#include <cstdint>

#define T_STEPS 200
#define BATCH   256
#define IN_F    512
#define H1      1024
#define H2      1024
#define H3      512
#define NCTA    128
#define WPAD    12          // weight row stride (floats) for 4-col gather
#define WPAD2   6           // weight row stride (floats) for 2-col gather
#define SBS     36          // sbits row stride in words (144B, 16B-aligned)

// ---------------- persistent device state ------------------------------------
__device__ float g_m3sum[BATCH * H3];
__device__ int   g_cnt[3];
__device__ unsigned g_xbits[T_STEPS * BATCH * (IN_F / 32)];
__device__ unsigned char g_bits1[T_STEPS][BATCH * 128];
__device__ unsigned char g_bits2[T_STEPS][BATCH * 128];
__device__ volatile int g_arrive[NCTA];
__device__ volatile int g_release;

// ---------------- prep ---------------------------------------------------------
__global__ void init_kernel() {
    int i = blockIdx.x * blockDim.x + threadIdx.x;
    if (i < 3) g_cnt[i] = 0;
    if (i < NCTA) g_arrive[i] = 0;
    if (i == 0) g_release = 0;
}

__global__ void build_xbits(const float* __restrict__ s) {
    int j = blockIdx.x * blockDim.x + threadIdx.x;
    if (j < T_STEPS * BATCH * (IN_F / 32)) {
        const float4* p = (const float4*)(s + (size_t)j * 32);
        unsigned b = 0;
#pragma unroll
        for (int q = 0; q < 8; q++) {
            float4 v = p[q];
            b |= (v.x > 0.5f ? 1u : 0u) << (4 * q + 0);
            b |= (v.y > 0.5f ? 1u : 0u) << (4 * q + 1);
            b |= (v.z > 0.5f ? 1u : 0u) << (4 * q + 2);
            b |= (v.w > 0.5f ? 1u : 0u) << (4 * q + 3);
        }
        g_xbits[j] = b;
    }
}

// ---------------- global barrier ----------------------------------------------
__device__ __forceinline__ void gbar(int gen, int cta, int tid) {
    __syncthreads();
    if (tid == 0) { __threadfence(); g_arrive[cta] = gen; }
    if (cta == 0 && tid < 32) {
        for (;;) {
            int v0 = g_arrive[tid];
            int v1 = g_arrive[tid + 32];
            int v2 = g_arrive[tid + 64];
            int v3 = g_arrive[tid + 96];
            if (__all_sync(0xFFFFFFFFu,
                           v0 >= gen && v1 >= gen && v2 >= gen && v3 >= gen))
                break;
        }
        if (tid == 0) { __threadfence(); g_release = gen; }
    }
    if (tid == 0) {
        while (g_release < gen) { }
        __threadfence();
    }
    __syncthreads();
}

// ---------------- cp.async helpers --------------------------------------------
__device__ __forceinline__ uint32_t smem_u32(const void* p) {
    uint32_t a;
    asm("{ .reg .u64 t; cvta.to.shared.u64 t, %1; cvt.u32.u64 %0, t; }" : "=r"(a) : "l"(p));
    return a;
}
__device__ __forceinline__ void cp_async16(uint32_t dst, const void* src) {
    asm volatile("cp.async.cg.shared.global [%0], [%1], 16;" :: "r"(dst), "l"(src));
}
__device__ __forceinline__ void cp_commit() {
    asm volatile("cp.async.commit_group;" ::: "memory");
}
__device__ __forceinline__ void cp_wait0() {
    asm volatile("cp.async.wait_group 0;" ::: "memory");
}

// ---------------- one layer phase: all 200 steps -------------------------------
// 512 threads: tid = 2*row + half. CPT cols per thread (CTA owns 2*CPT cols).
// srcbits: [t][row][KW words]. dstbits (HAS_SPK): [t][row][128] bytes.
template<int KW, int CPT, bool HAS_SPK, bool HAS_SUM>
__device__ __forceinline__ void phase_loop(const unsigned* __restrict__ srcbits,
                                           unsigned char* __restrict__ dstbits,
                                           const float* __restrict__ Wsm,
                                           uint32_t sb_u32,          // sbits smem addr
                                           unsigned* __restrict__ sb,
                                           const float* __restrict__ bias_g,
                                           float beta, int cta, int tid,
                                           float* m, float* msum, int& cnt)
{
    constexpr int CH  = KW / 4;            // uint4 chunks per row
    constexpr int NCH = (BATCH * CH) / 512;
    constexpr int WS  = (CPT == 4) ? WPAD : WPAD2;
    constexpr int BUFB = BATCH * SBS * 4;  // bytes per sbits buffer

    const int row  = tid >> 1;
    const int half = tid & 1;
    const int colbase = cta * (2 * CPT) + half * CPT;

    float bs[CPT];
#pragma unroll
    for (int j = 0; j < CPT; j++) bs[j] = bias_g[colbase + j];

    // prologue: stage t=0 into buffer 0
#pragma unroll
    for (int i = 0; i < NCH; i++) {
        int c = tid + i * 512;
        int r = c / CH, j = c % CH;
        cp_async16(sb_u32 + (r * SBS + j * 4) * 4,
                   srcbits + (size_t)r * KW + j * 4);
    }
    cp_commit(); cp_wait0();
    __syncthreads();

    int buf = 0;
    for (int t = 0; t < T_STEPS; t++) {
        // issue staging of t+1 into other buffer (overlaps compute)
        if (t + 1 < T_STEPS) {
            const unsigned* nsrc = srcbits + (size_t)(t + 1) * BATCH * KW;
            uint32_t ndst = sb_u32 + (buf ^ 1) * BUFB;
#pragma unroll
            for (int i = 0; i < NCH; i++) {
                int c = tid + i * 512;
                int r = c / CH, j = c % CH;
                cp_async16(ndst + (r * SBS + j * 4) * 4,
                           nsrc + (size_t)r * KW + j * 4);
            }
            cp_commit();
        }

        // ---- sparse gather over this row's bits ----
        float a[CPT];
#pragma unroll
        for (int j = 0; j < CPT; j++) a[j] = bs[j];

        const unsigned* rb = sb + buf * (BATCH * SBS) + row * SBS;
        for (int wg = 0; wg < CH; wg++) {
            uint4 v = *(const uint4*)(rb + wg * 4);
            if ((v.x | v.y | v.z | v.w) == 0) continue;
#pragma unroll
            for (int sub = 0; sub < 4; sub++) {
                unsigned w = (sub == 0) ? v.x : (sub == 1) ? v.y
                           : (sub == 2) ? v.z : v.w;
                const int kbase = (wg * 4 + sub) * 32;
                while (w) {
                    int b = __ffs(w) - 1;
                    w &= w - 1;
                    int k = kbase + b;
                    if (CPT == 4) {
                        float4 wv = *(const float4*)(Wsm + k * WPAD + half * 4);
                        a[0] += wv.x; a[1] += wv.y;
                        a[2] += wv.z; a[3] += wv.w;
                    } else {
                        float2 wv = *(const float2*)(Wsm + k * WPAD2 + half * 2);
                        a[0] += wv.x; a[1] += wv.y;
                    }
                }
            }
        }

        // ---- LIF update ----
        unsigned nib = 0;
#pragma unroll
        for (int j = 0; j < CPT; j++) {
            float mm = m[j];
            float reset = (mm > 1.0f) ? 1.0f : 0.0f;   // spike(m_prev - 1)
            mm = beta * mm + a[j] - reset;             // subtract-reset
            unsigned sp = (mm > 1.0f) ? 1u : 0u;       // spike(m_new - 1)
            m[j] = mm;
            if (HAS_SUM) msum[j] += mm;
            nib |= sp << j;
        }
        // merge halves (lanes 2r, 2r+1 adjacent)
        unsigned other = __shfl_down_sync(0xFFFFFFFFu, nib, 1);
        if (half == 0) {
            unsigned full = nib | (other << CPT);
            cnt += __popc(full);
            if (HAS_SPK)
                dstbits[(size_t)t * (BATCH * 128) + row * 128 + cta] =
                    (unsigned char)full;
        }

        if (t + 1 < T_STEPS) cp_wait0();
        __syncthreads();
        buf ^= 1;
    }
}

// ---------------- THE persistent kernel ----------------------------------------
__global__ void __launch_bounds__(512, 1)
snn_phased(const float* __restrict__ W1, const float* __restrict__ b1,
           const float* __restrict__ W2, const float* __restrict__ b2,
           const float* __restrict__ W3, const float* __restrict__ b3)
{
    extern __shared__ float smem[];
    float* Wsm = smem;                              // up to 1024*12 floats (48KB)
    unsigned* sb = (unsigned*)(Wsm + 1024 * WPAD);  // 2 buffers of 256*36 words
    uint32_t sb_u32 = smem_u32(sb);

    const int tid = threadIdx.x;
    const int cta = blockIdx.x;
    const int wid = tid >> 5, lane = tid & 31;

    const float BETA1 = 0.81873075307798182f;  // exp(-1/5)
    const float BETA2 = 0.90483741803595957f;  // exp(-1/10)
    const float BETA3 = 0.95122942450071402f;  // exp(-1/20)

    int c1 = 0, c2 = 0, c3 = 0;

    // ================= phase 1: layer 1 =================
    {
        for (int i = tid; i < 8 * IN_F; i += 512) {
            int c = i >> 9, k = i & (IN_F - 1);
            Wsm[k * WPAD + c] = W1[(size_t)(8 * cta + c) * IN_F + k];
        }
        float m1[4] = {0, 0, 0, 0};
        __syncthreads();
        phase_loop<16, 4, true, false>(g_xbits, &g_bits1[0][0], Wsm, sb_u32, sb,
                                       b1, BETA1, cta, tid, m1, nullptr, c1);
    }
    gbar(1, cta, tid);

    // ================= phase 2: layer 2 =================
    {
        for (int i = tid; i < 8 * H1; i += 512) {
            int c = i >> 10, k = i & (H1 - 1);
            Wsm[k * WPAD + c] = W2[(size_t)(8 * cta + c) * H1 + k];
        }
        float m2[4] = {0, 0, 0, 0};
        __syncthreads();
        phase_loop<32, 4, true, false>((const unsigned*)&g_bits1[0][0], &g_bits2[0][0],
                                       Wsm, sb_u32, sb, b2, BETA2, cta, tid,
                                       m2, nullptr, c2);
    }
    gbar(2, cta, tid);

    // ================= phase 3: layer 3 =================
    {
        for (int i = tid; i < 4 * H2; i += 512) {
            int c = i >> 10, k = i & (H2 - 1);
            Wsm[k * WPAD2 + c] = W3[(size_t)(4 * cta + c) * H2 + k];
        }
        float m3[2] = {0, 0}, ms[2] = {0, 0};
        __syncthreads();
        phase_loop<32, 2, false, true>((const unsigned*)&g_bits2[0][0], nullptr,
                                       Wsm, sb_u32, sb, b3, BETA3, cta, tid,
                                       m3, ms, c3);
        // write m3sum slice: row, cols 4*cta + half*2 .. +1
        const int row = tid >> 1, half = tid & 1;
        *(float2*)(g_m3sum + (size_t)row * H3 + 4 * cta + half * 2) =
            make_float2(ms[0], ms[1]);
    }

    // ---- exact spike counts ----
#pragma unroll
    for (int o = 16; o > 0; o >>= 1) {
        c1 += __shfl_down_sync(0xFFFFFFFFu, c1, o);
        c2 += __shfl_down_sync(0xFFFFFFFFu, c2, o);
        c3 += __shfl_down_sync(0xFFFFFFFFu, c3, o);
    }
    __shared__ int sr_[3][16];
    if (lane == 0) { sr_[0][wid] = c1; sr_[1][wid] = c2; sr_[2][wid] = c3; }
    __syncthreads();
    if (tid < 3) {
        int s = 0;
#pragma unroll
        for (int w = 0; w < 16; w++) s += sr_[tid][w];
        atomicAdd(&g_cnt[tid], s);
    }
}

// ---------------- readout -------------------------------------------------------
__global__ void final_kernel(const float* __restrict__ Wr,
                             const float* __restrict__ br,
                             float* __restrict__ out)
{
    const int b = blockIdx.x;
    const int t = threadIdx.x;
    float a0 = 0.f, a1 = 0.f;
    for (int j = t; j < H3; j += 128) {
        float v = g_m3sum[(size_t)b * H3 + j] / (float)T_STEPS;
        a0 = fmaf(v, Wr[j],      a0);
        a1 = fmaf(v, Wr[H3 + j], a1);
    }
    __shared__ float s0[128], s1[128];
    s0[t] = a0; s1[t] = a1;
    __syncthreads();
    for (int o = 64; o > 0; o >>= 1) {
        if (t < o) { s0[t] += s0[t + o]; s1[t] += s1[t + o]; }
        __syncthreads();
    }
    if (t == 0) {
        out[b * 2 + 0] = s0[0] + br[0];
        out[b * 2 + 1] = s1[0] + br[1];
    }
    if (b == 0 && t < 3) {
        float denom = (t == 0) ? (float)((double)T_STEPS * BATCH * H1)
                    : (t == 1) ? (float)((double)T_STEPS * BATCH * H2)
                               : (float)((double)T_STEPS * BATCH * H3);
        out[BATCH * 2 + t] = (float)g_cnt[t] / denom;
    }
}

// ---------------- launch --------------------------------------------------------
extern "C" void kernel_launch(void* const* d_in, const int* in_sizes, int n_in,
                              void* d_out, int out_size)
{
    const float* spikes = (const float*)d_in[0];
    const float* W1 = (const float*)d_in[1];
    const float* b1 = (const float*)d_in[2];
    const float* W2 = (const float*)d_in[3];
    const float* b2 = (const float*)d_in[4];
    const float* W3 = (const float*)d_in[5];
    const float* b3 = (const float*)d_in[6];
    const float* Wr = (const float*)d_in[7];
    const float* br = (const float*)d_in[8];
    float* out = (float*)d_out;

    // smem: weights 48KB + 2 sbits buffers (2 * 256*36*4 = 73728) = 122880 B
    const int DSMEM = 1024 * WPAD * 4 + 2 * BATCH * SBS * 4;
    cudaFuncSetAttribute(snn_phased,
                         cudaFuncAttributeMaxDynamicSharedMemorySize, DSMEM);

    init_kernel<<<1, 256>>>();
    {
        int n = T_STEPS * BATCH * (IN_F / 32);
        build_xbits<<<(n + 255) / 256, 256>>>(spikes);
    }
    snn_phased<<<NCTA, 512, DSMEM>>>(W1, b1, W2, b2, W3, b3);
    final_kernel<<<BATCH, 128>>>(Wr, br, out);
}

// round 10
// speedup vs baseline: 22.2302x; 1.5531x over previous
#include <cuda_runtime.h>
#include <cstdint>

#define T_STEPS 200
#define BATCH   256
#define IN_F    512
#define H1      1024
#define H2      1024
#define H3      512
#define NCTA    128
#define SW1     65      // phase-1 weight row stride (floats), conflict-free
#define SW2     33      // phase-2/3 weight row stride

// ---------------- persistent device state ------------------------------------
__device__ float g_m3sum[BATCH * H3];
__device__ int   g_cnt[3];
__device__ unsigned g_xbits[T_STEPS * BATCH * 16];       // [t][row][16 words]
__device__ unsigned g_b1[T_STEPS][BATCH][32];            // spk1 history
__device__ unsigned g_b2[T_STEPS][BATCH][32];            // spk2 history
__device__ volatile int g_arrive[NCTA];
__device__ volatile int g_release;

// ---------------- prep ---------------------------------------------------------
__global__ void init_kernel() {
    int i = blockIdx.x * blockDim.x + threadIdx.x;
    if (i < 3) g_cnt[i] = 0;
    if (i < NCTA) g_arrive[i] = 0;
    if (i == 0) g_release = 0;
}

__global__ void build_xbits(const float* __restrict__ s) {
    int j = blockIdx.x * blockDim.x + threadIdx.x;
    if (j < T_STEPS * BATCH * 16) {
        const float4* p = (const float4*)(s + (size_t)j * 32);
        unsigned b = 0;
#pragma unroll
        for (int q = 0; q < 8; q++) {
            float4 v = p[q];
            b |= (v.x > 0.5f ? 1u : 0u) << (4 * q + 0);
            b |= (v.y > 0.5f ? 1u : 0u) << (4 * q + 1);
            b |= (v.z > 0.5f ? 1u : 0u) << (4 * q + 2);
            b |= (v.w > 0.5f ? 1u : 0u) << (4 * q + 3);
        }
        g_xbits[j] = b;
    }
}

// ---------------- global barrier ----------------------------------------------
__device__ __forceinline__ void gbar(int gen, int cta, int tid) {
    __syncthreads();
    if (tid == 0) { __threadfence(); g_arrive[cta] = gen; }
    if (cta == 0 && tid < 32) {
        for (;;) {
            int v0 = g_arrive[tid];
            int v1 = g_arrive[tid + 32];
            int v2 = g_arrive[tid + 64];
            int v3 = g_arrive[tid + 96];
            if (__all_sync(0xFFFFFFFFu,
                           v0 >= gen && v1 >= gen && v2 >= gen && v3 >= gen))
                break;
        }
        if (tid == 0) { __threadfence(); g_release = gen; }
    }
    if (tid == 0) {
        while (g_release < gen) { }
        __threadfence();
    }
    __syncthreads();
}

// ---------------- LIF scalar step ----------------------------------------------
__device__ __forceinline__ unsigned lif1(float& m, float a, float beta) {
    float reset = (m > 1.0f) ? 1.0f : 0.0f;    // spike(m_prev - 1)
    m = beta * m + a - reset;                  // subtract-reset
    return (m > 1.0f) ? 1u : 0u;               // spike(m_new - 1)
}

// ---------------- THE persistent kernel ----------------------------------------
__global__ void __launch_bounds__(512, 1)
snn_phased(const float* __restrict__ W1, const float* __restrict__ b1,
           const float* __restrict__ W2, const float* __restrict__ b2,
           const float* __restrict__ W3, const float* __restrict__ b3)
{
    extern __shared__ float Wsm[];     // phase1: [512][65]; phase2/3: [1024][33]
    __shared__ int sr_[3][16];

    const int tid  = threadIdx.x;
    const int cta  = blockIdx.x;
    const int wid  = tid >> 5;
    const int lane = tid & 31;

    const float BETA1 = 0.81873075307798182f;  // exp(-1/5)
    const float BETA2 = 0.90483741803595957f;  // exp(-1/10)
    const float BETA3 = 0.95122942450071402f;  // exp(-1/20)

    int c1 = 0, c2 = 0, c3 = 0;

    // ================= phase 1: layer 1 (64 cols x 32 rows per CTA) ==========
    {
        const int cb = cta & 15;        // 16 col-blocks of 64
        const int rg = cta >> 4;        // 8 row-groups of 32
        for (int idx = tid; idx < 64 * IN_F; idx += 512) {
            int n = idx >> 9, k = idx & (IN_F - 1);
            Wsm[k * SW1 + n] = W1[(size_t)(cb * 64 + n) * IN_F + k];
        }
        const int r0 = rg * 32 + wid * 2;          // warp owns rows r0, r0+1
        const float bs0 = b1[cb * 64 + lane];
        const float bs1 = b1[cb * 64 + 32 + lane];
        float m[2][2] = {{0.f, 0.f}, {0.f, 0.f}};
        __syncthreads();

        // lane holds word (lane&15) of row r0 + (lane>>4)
        unsigned cur = __ldcg(&g_xbits[(size_t)(0 * BATCH + r0) * 16 + lane]);
        for (int t = 0; t < T_STEPS; t++) {
            unsigned nxt = 0;
            if (t + 1 < T_STEPS)
                nxt = __ldcg(&g_xbits[(size_t)((t + 1) * BATCH + r0) * 16 + lane]);
#pragma unroll
            for (int i = 0; i < 2; i++) {
                float a0 = bs0, a1 = bs1;
#pragma unroll
                for (int w = 0; w < 16; w++) {
                    unsigned bits = __shfl_sync(0xFFFFFFFFu, cur, i * 16 + w);
                    while (bits) {
                        int b = __ffs(bits) - 1;
                        bits &= bits - 1;
                        const float* wp = Wsm + (w * 32 + b) * SW1 + lane;
                        a0 += wp[0];
                        a1 += wp[32];
                    }
                }
                unsigned s0 = lif1(m[i][0], a0, BETA1);
                unsigned s1 = lif1(m[i][1], a1, BETA1);
                unsigned w0 = __ballot_sync(0xFFFFFFFFu, s0);
                unsigned w1 = __ballot_sync(0xFFFFFFFFu, s1);
                if (lane == 0) {
                    c1 += __popc(w0) + __popc(w1);
                    *(unsigned long long*)&g_b1[t][r0 + i][cb * 2] =
                        ((unsigned long long)w1 << 32) | w0;
                }
            }
            cur = nxt;
        }
    }
    gbar(1, cta, tid);

    // ================= phase 2: layer 2 (32 cols x 64 rows per CTA) ==========
    {
        const int cb = cta & 31;        // 32 col-blocks of 32
        const int rg = cta >> 5;        // 4 row-groups of 64
        for (int idx = tid; idx < 32 * H1; idx += 512) {
            int n = idx >> 10, k = idx & (H1 - 1);
            Wsm[k * SW2 + n] = W2[(size_t)(cb * 32 + n) * H1 + k];
        }
        const int r0 = rg * 64 + wid * 4;          // warp owns rows r0..r0+3
        const float bsv = b2[cb * 32 + lane];
        float m[4] = {0.f, 0.f, 0.f, 0.f};
        __syncthreads();

        unsigned cur[4];
#pragma unroll
        for (int c = 0; c < 4; c++) cur[c] = __ldcg(&g_b1[0][r0 + c][lane]);
        for (int t = 0; t < T_STEPS; t++) {
            unsigned nxt[4] = {0, 0, 0, 0};
            if (t + 1 < T_STEPS) {
#pragma unroll
                for (int c = 0; c < 4; c++)
                    nxt[c] = __ldcg(&g_b1[t + 1][r0 + c][lane]);
            }
#pragma unroll
            for (int i = 0; i < 4; i++) {
                float a = bsv;
                unsigned nz = __ballot_sync(0xFFFFFFFFu, cur[i] != 0u);
                while (nz) {
                    int w = __ffs(nz) - 1;
                    nz &= nz - 1;
                    unsigned bits = __shfl_sync(0xFFFFFFFFu, cur[i], w);
                    while (bits) {
                        int b = __ffs(bits) - 1;
                        bits &= bits - 1;
                        a += Wsm[(w * 32 + b) * SW2 + lane];
                    }
                }
                unsigned s = lif1(m[i], a, BETA2);
                unsigned w0 = __ballot_sync(0xFFFFFFFFu, s);
                if (lane == 0) {
                    c2 += __popc(w0);
                    g_b2[t][r0 + i][cb] = w0;
                }
            }
#pragma unroll
            for (int c = 0; c < 4; c++) cur[c] = nxt[c];
        }
    }
    gbar(2, cta, tid);

    // ================= phase 3: layer 3 (32 cols x 32 rows per CTA) ==========
    {
        const int cb = cta & 15;        // 16 col-blocks of 32
        const int rg = cta >> 4;        // 8 row-groups of 32
        for (int idx = tid; idx < 32 * H2; idx += 512) {
            int n = idx >> 10, k = idx & (H2 - 1);
            Wsm[k * SW2 + n] = W3[(size_t)(cb * 32 + n) * H2 + k];
        }
        const int r0 = rg * 32 + wid * 2;          // warp owns rows r0, r0+1
        const float bsv = b3[cb * 32 + lane];
        float m[2] = {0.f, 0.f}, ms[2] = {0.f, 0.f};
        __syncthreads();

        unsigned cur[2];
#pragma unroll
        for (int c = 0; c < 2; c++) cur[c] = __ldcg(&g_b2[0][r0 + c][lane]);
        for (int t = 0; t < T_STEPS; t++) {
            unsigned nxt[2] = {0, 0};
            if (t + 1 < T_STEPS) {
#pragma unroll
                for (int c = 0; c < 2; c++)
                    nxt[c] = __ldcg(&g_b2[t + 1][r0 + c][lane]);
            }
#pragma unroll
            for (int i = 0; i < 2; i++) {
                float a = bsv;
                unsigned nz = __ballot_sync(0xFFFFFFFFu, cur[i] != 0u);
                while (nz) {
                    int w = __ffs(nz) - 1;
                    nz &= nz - 1;
                    unsigned bits = __shfl_sync(0xFFFFFFFFu, cur[i], w);
                    while (bits) {
                        int b = __ffs(bits) - 1;
                        bits &= bits - 1;
                        a += Wsm[(w * 32 + b) * SW2 + lane];
                    }
                }
                unsigned s = lif1(m[i], a, BETA3);
                ms[i] += m[i];
                unsigned w0 = __ballot_sync(0xFFFFFFFFu, s);
                if (lane == 0) c3 += __popc(w0);
            }
#pragma unroll
            for (int c = 0; c < 2; c++) cur[c] = nxt[c];
        }
        // write m3sum slice: rows r0..r0+1, col cb*32 + lane
#pragma unroll
        for (int i = 0; i < 2; i++)
            g_m3sum[(size_t)(r0 + i) * H3 + cb * 32 + lane] = ms[i];
    }

    // ---- exact spike counts (partials live on lane 0 of each warp) ----
    if (lane == 0) { sr_[0][wid] = c1; sr_[1][wid] = c2; sr_[2][wid] = c3; }
    __syncthreads();
    if (tid < 3) {
        int s = 0;
#pragma unroll
        for (int w = 0; w < 16; w++) s += sr_[tid][w];
        atomicAdd(&g_cnt[tid], s);
    }
}

// ---------------- readout -------------------------------------------------------
__global__ void final_kernel(const float* __restrict__ Wr,
                             const float* __restrict__ br,
                             float* __restrict__ out)
{
    const int b = blockIdx.x;
    const int t = threadIdx.x;
    float a0 = 0.f, a1 = 0.f;
    for (int j = t; j < H3; j += 128) {
        float v = g_m3sum[(size_t)b * H3 + j] / (float)T_STEPS;
        a0 = fmaf(v, Wr[j],      a0);
        a1 = fmaf(v, Wr[H3 + j], a1);
    }
    __shared__ float s0[128], s1[128];
    s0[t] = a0; s1[t] = a1;
    __syncthreads();
    for (int o = 64; o > 0; o >>= 1) {
        if (t < o) { s0[t] += s0[t + o]; s1[t] += s1[t + o]; }
        __syncthreads();
    }
    if (t == 0) {
        out[b * 2 + 0] = s0[0] + br[0];
        out[b * 2 + 1] = s1[0] + br[1];
    }
    if (b == 0 && t < 3) {
        float denom = (t == 0) ? (float)((double)T_STEPS * BATCH * H1)
                    : (t == 1) ? (float)((double)T_STEPS * BATCH * H2)
                               : (float)((double)T_STEPS * BATCH * H3);
        out[BATCH * 2 + t] = (float)g_cnt[t] / denom;
    }
}

// ---------------- launch --------------------------------------------------------
extern "C" void kernel_launch(void* const* d_in, const int* in_sizes, int n_in,
                              void* d_out, int out_size)
{
    const float* spikes = (const float*)d_in[0];
    const float* W1 = (const float*)d_in[1];
    const float* b1 = (const float*)d_in[2];
    const float* W2 = (const float*)d_in[3];
    const float* b2 = (const float*)d_in[4];
    const float* W3 = (const float*)d_in[5];
    const float* b3 = (const float*)d_in[6];
    const float* Wr = (const float*)d_in[7];
    const float* br = (const float*)d_in[8];
    float* out = (float*)d_out;

    const int DSMEM = 1024 * SW2 * 4;   // 135,168 B (covers phase 1's 512*65*4 too)
    cudaFuncSetAttribute(snn_phased,
                         cudaFuncAttributeMaxDynamicSharedMemorySize, DSMEM);

    init_kernel<<<1, 256>>>();
    {
        int n = T_STEPS * BATCH * 16;
        build_xbits<<<(n + 255) / 256, 256>>>(spikes);
    }
    snn_phased<<<NCTA, 512, DSMEM>>>(W1, b1, W2, b2, W3, b3);
    final_kernel<<<BATCH, 128>>>(Wr, br, out);
}

// round 11
// speedup vs baseline: 29.6360x; 1.3331x over previous
#include <cuda_runtime.h>
#include <cstdint>

#define T_STEPS 200
#define BATCH   256
#define IN_F    512
#define H1      1024
#define H2      1024
#define H3      512
#define NCTA    128
#define SW2     33      // phase-2/3 weight row stride (floats)
#define IDXCAP  544     // per-(t,row) index list capacity (max 519 + slack)

// ---------------- persistent device state ------------------------------------
__device__ float g_m3sum[BATCH * H3];
__device__ int   g_cnt[3];
__device__ unsigned g_xbits[T_STEPS * BATCH * 16];        // [t][row][16 words]
__device__ unsigned short g_xidx[T_STEPS][BATCH][IDXCAP]; // compacted k lists
__device__ int g_xcnt[T_STEPS][BATCH];                    // padded counts (mult of 8)
__device__ unsigned g_b1[T_STEPS][BATCH][32];             // spk1 history
__device__ unsigned g_b2[T_STEPS][BATCH][32];             // spk2 history
__device__ volatile int g_arrive[NCTA];
__device__ volatile int g_release;

// ---------------- prep ---------------------------------------------------------
__global__ void init_kernel() {
    int i = blockIdx.x * blockDim.x + threadIdx.x;
    if (i < 3) g_cnt[i] = 0;
    if (i < NCTA) g_arrive[i] = 0;
    if (i == 0) g_release = 0;
}

__global__ void build_xbits(const float* __restrict__ s) {
    int j = blockIdx.x * blockDim.x + threadIdx.x;
    if (j < T_STEPS * BATCH * 16) {
        const float4* p = (const float4*)(s + (size_t)j * 32);
        unsigned b = 0;
#pragma unroll
        for (int q = 0; q < 8; q++) {
            float4 v = p[q];
            b |= (v.x > 0.5f ? 1u : 0u) << (4 * q + 0);
            b |= (v.y > 0.5f ? 1u : 0u) << (4 * q + 1);
            b |= (v.z > 0.5f ? 1u : 0u) << (4 * q + 2);
            b |= (v.w > 0.5f ? 1u : 0u) << (4 * q + 3);
        }
        g_xbits[j] = b;
    }
}

// one thread per (t,row): compact active k's (ascending), pad to multiple of 8
__global__ void build_xidx() {
    int id = blockIdx.x * blockDim.x + threadIdx.x;
    if (id >= T_STEPS * BATCH) return;
    int t = id / BATCH, r = id % BATCH;
    const unsigned* wp = &g_xbits[(size_t)id * 16];
    unsigned short* dst = g_xidx[t][r];
    int n = 0;
#pragma unroll
    for (int w = 0; w < 16; w++) {
        unsigned bits = wp[w];
        while (bits) {
            int b = __ffs(bits) - 1;
            bits &= bits - 1;
            dst[n++] = (unsigned short)(w * 32 + b);
        }
    }
    int np = (n + 7) & ~7;
    while (n < np) dst[n++] = (unsigned short)IN_F;   // dummy -> zero weight row
    g_xcnt[t][r] = np;
}

// ---------------- global barrier ----------------------------------------------
__device__ __forceinline__ void gbar(int gen, int cta, int tid) {
    __syncthreads();
    if (tid == 0) { __threadfence(); g_arrive[cta] = gen; }
    if (cta == 0 && tid < 32) {
        for (;;) {
            int v0 = g_arrive[tid];
            int v1 = g_arrive[tid + 32];
            int v2 = g_arrive[tid + 64];
            int v3 = g_arrive[tid + 96];
            if (__all_sync(0xFFFFFFFFu,
                           v0 >= gen && v1 >= gen && v2 >= gen && v3 >= gen))
                break;
        }
        if (tid == 0) { __threadfence(); g_release = gen; }
    }
    if (tid == 0) {
        while (g_release < gen) { }
        __threadfence();
    }
    __syncthreads();
}

// ---------------- LIF scalar step ----------------------------------------------
__device__ __forceinline__ unsigned lif1(float& m, float a, float beta) {
    float reset = (m > 1.0f) ? 1.0f : 0.0f;    // spike(m_prev - 1)
    m = beta * m + a - reset;                  // subtract-reset
    return (m > 1.0f) ? 1u : 0u;               // spike(m_new - 1)
}

// ---------------- THE persistent kernel ----------------------------------------
__global__ void __launch_bounds__(512, 1)
snn_phased(const float* __restrict__ W1, const float* __restrict__ b1,
           const float* __restrict__ W2, const float* __restrict__ b2,
           const float* __restrict__ W3, const float* __restrict__ b3)
{
    extern __shared__ float Wsm[];   // phase1: float2[513][32]; phase2/3: [1024][33]
    __shared__ int sr_[3][16];

    const int tid  = threadIdx.x;
    const int cta  = blockIdx.x;
    const int wid  = tid >> 5;
    const int lane = tid & 31;

    const float BETA1 = 0.81873075307798182f;  // exp(-1/5)
    const float BETA2 = 0.90483741803595957f;  // exp(-1/10)
    const float BETA3 = 0.95122942450071402f;  // exp(-1/20)

    int c1 = 0, c2 = 0, c3 = 0;

    // ================= phase 1: layer 1 (64 cols x 32 rows per CTA) ==========
    {
        float2* Wp2 = (float2*)Wsm;     // Wp2[k*32 + lane] = (W[c0+lane][k], W[c0+32+lane][k])
        const int cb = cta & 15;        // 16 col-blocks of 64
        const int rg = cta >> 4;        // 8 row-groups of 32
        // stage weights: coalesced LDG over (c,k), strided STS (2-way, once)
        for (int idx = tid; idx < 64 * IN_F; idx += 512) {
            int c = idx >> 9, k = idx & (IN_F - 1);
            Wsm[k * 64 + (c & 31) * 2 + (c >> 5)] =
                W1[(size_t)(cb * 64 + c) * IN_F + k];
        }
        // zero dummy row k = IN_F
        if (tid < 64) Wsm[IN_F * 64 + tid] = 0.f;

        const int r0 = rg * 32 + wid * 2;          // warp owns rows r0, r0+1
        const float bs0 = b1[cb * 64 + lane];
        const float bs1 = b1[cb * 64 + 32 + lane];
        float m[2][2] = {{0.f, 0.f}, {0.f, 0.f}};
        __syncthreads();

        // prefetch t=0 counts + first index chunks
        int pn[2], pidx[2];
#pragma unroll
        for (int i = 0; i < 2; i++) {
            pn[i]   = __ldcg(&g_xcnt[0][r0 + i]);
            pidx[i] = __ldcg(&g_xidx[0][r0 + i][lane]);
        }

        for (int t = 0; t < T_STEPS; t++) {
            int nn[2]  = {pn[0], pn[1]};
            int ic0[2] = {pidx[0], pidx[1]};
            if (t + 1 < T_STEPS) {
#pragma unroll
                for (int i = 0; i < 2; i++) {
                    pn[i]   = __ldcg(&g_xcnt[t + 1][r0 + i]);
                    pidx[i] = __ldcg(&g_xidx[t + 1][r0 + i][lane]);
                }
            }
#pragma unroll
            for (int i = 0; i < 2; i++) {
                float a0 = bs0, a1 = bs1;
                const unsigned short* lp = g_xidx[t][r0 + i];
                int idxv = ic0[i];
                const int n = nn[i];
                for (int base = 0; base < n; base += 32) {
                    if (base > 0) idxv = __ldcg(&lp[base + lane]);
                    const int m8 = min(n - base, 32);
                    for (int jb = 0; jb < m8; jb += 8) {
#pragma unroll
                        for (int u = 0; u < 8; u++) {
                            int k = __shfl_sync(0xFFFFFFFFu, idxv, jb + u);
                            float2 w = Wp2[k * 32 + lane];
                            a0 += w.x;
                            a1 += w.y;
                        }
                    }
                }
                unsigned s0 = lif1(m[i][0], a0, BETA1);
                unsigned s1 = lif1(m[i][1], a1, BETA1);
                unsigned w0 = __ballot_sync(0xFFFFFFFFu, s0);
                unsigned w1 = __ballot_sync(0xFFFFFFFFu, s1);
                if (lane == 0) {
                    c1 += __popc(w0) + __popc(w1);
                    *(unsigned long long*)&g_b1[t][r0 + i][cb * 2] =
                        ((unsigned long long)w1 << 32) | w0;
                }
            }
        }
    }
    gbar(1, cta, tid);

    // ================= phase 2: layer 2 (32 cols x 64 rows per CTA) ==========
    {
        const int cb = cta & 31;        // 32 col-blocks of 32
        const int rg = cta >> 5;        // 4 row-groups of 64
        for (int idx = tid; idx < 32 * H1; idx += 512) {
            int n = idx >> 10, k = idx & (H1 - 1);
            Wsm[k * SW2 + n] = W2[(size_t)(cb * 32 + n) * H1 + k];
        }
        const int r0 = rg * 64 + wid * 4;          // warp owns rows r0..r0+3
        const float bsv = b2[cb * 32 + lane];
        float m[4] = {0.f, 0.f, 0.f, 0.f};
        __syncthreads();

        unsigned cur[4];
#pragma unroll
        for (int c = 0; c < 4; c++) cur[c] = __ldcg(&g_b1[0][r0 + c][lane]);
        for (int t = 0; t < T_STEPS; t++) {
            unsigned nxt[4] = {0, 0, 0, 0};
            if (t + 1 < T_STEPS) {
#pragma unroll
                for (int c = 0; c < 4; c++)
                    nxt[c] = __ldcg(&g_b1[t + 1][r0 + c][lane]);
            }
#pragma unroll
            for (int i = 0; i < 4; i++) {
                float a = bsv;
                unsigned nz = __ballot_sync(0xFFFFFFFFu, cur[i] != 0u);
                while (nz) {
                    int w = __ffs(nz) - 1;
                    nz &= nz - 1;
                    unsigned bits = __shfl_sync(0xFFFFFFFFu, cur[i], w);
                    while (bits) {
                        int b = __ffs(bits) - 1;
                        bits &= bits - 1;
                        a += Wsm[(w * 32 + b) * SW2 + lane];
                    }
                }
                unsigned s = lif1(m[i], a, BETA2);
                unsigned w0 = __ballot_sync(0xFFFFFFFFu, s);
                if (lane == 0) {
                    c2 += __popc(w0);
                    g_b2[t][r0 + i][cb] = w0;
                }
            }
#pragma unroll
            for (int c = 0; c < 4; c++) cur[c] = nxt[c];
        }
    }
    gbar(2, cta, tid);

    // ================= phase 3: layer 3 (32 cols x 32 rows per CTA) ==========
    {
        const int cb = cta & 15;        // 16 col-blocks of 32
        const int rg = cta >> 4;        // 8 row-groups of 32
        for (int idx = tid; idx < 32 * H2; idx += 512) {
            int n = idx >> 10, k = idx & (H2 - 1);
            Wsm[k * SW2 + n] = W3[(size_t)(cb * 32 + n) * H2 + k];
        }
        const int r0 = rg * 32 + wid * 2;          // warp owns rows r0, r0+1
        const float bsv = b3[cb * 32 + lane];
        float m[2] = {0.f, 0.f}, ms[2] = {0.f, 0.f};
        __syncthreads();

        unsigned cur[2];
#pragma unroll
        for (int c = 0; c < 2; c++) cur[c] = __ldcg(&g_b2[0][r0 + c][lane]);
        for (int t = 0; t < T_STEPS; t++) {
            unsigned nxt[2] = {0, 0};
            if (t + 1 < T_STEPS) {
#pragma unroll
                for (int c = 0; c < 2; c++)
                    nxt[c] = __ldcg(&g_b2[t + 1][r0 + c][lane]);
            }
#pragma unroll
            for (int i = 0; i < 2; i++) {
                float a = bsv;
                unsigned nz = __ballot_sync(0xFFFFFFFFu, cur[i] != 0u);
                while (nz) {
                    int w = __ffs(nz) - 1;
                    nz &= nz - 1;
                    unsigned bits = __shfl_sync(0xFFFFFFFFu, cur[i], w);
                    while (bits) {
                        int b = __ffs(bits) - 1;
                        bits &= bits - 1;
                        a += Wsm[(w * 32 + b) * SW2 + lane];
                    }
                }
                unsigned s = lif1(m[i], a, BETA3);
                ms[i] += m[i];
                unsigned w0 = __ballot_sync(0xFFFFFFFFu, s);
                if (lane == 0) c3 += __popc(w0);
            }
#pragma unroll
            for (int c = 0; c < 2; c++) cur[c] = nxt[c];
        }
#pragma unroll
        for (int i = 0; i < 2; i++)
            g_m3sum[(size_t)(r0 + i) * H3 + cb * 32 + lane] = ms[i];
    }

    // ---- exact spike counts ----
    if (lane == 0) { sr_[0][wid] = c1; sr_[1][wid] = c2; sr_[2][wid] = c3; }
    __syncthreads();
    if (tid < 3) {
        int s = 0;
#pragma unroll
        for (int w = 0; w < 16; w++) s += sr_[tid][w];
        atomicAdd(&g_cnt[tid], s);
    }
}

// ---------------- readout -------------------------------------------------------
__global__ void final_kernel(const float* __restrict__ Wr,
                             const float* __restrict__ br,
                             float* __restrict__ out)
{
    const int b = blockIdx.x;
    const int t = threadIdx.x;
    float a0 = 0.f, a1 = 0.f;
    for (int j = t; j < H3; j += 128) {
        float v = g_m3sum[(size_t)b * H3 + j] / (float)T_STEPS;
        a0 = fmaf(v, Wr[j],      a0);
        a1 = fmaf(v, Wr[H3 + j], a1);
    }
    __shared__ float s0[128], s1[128];
    s0[t] = a0; s1[t] = a1;
    __syncthreads();
    for (int o = 64; o > 0; o >>= 1) {
        if (t < o) { s0[t] += s0[t + o]; s1[t] += s1[t + o]; }
        __syncthreads();
    }
    if (t == 0) {
        out[b * 2 + 0] = s0[0] + br[0];
        out[b * 2 + 1] = s1[0] + br[1];
    }
    if (b == 0 && t < 3) {
        float denom = (t == 0) ? (float)((double)T_STEPS * BATCH * H1)
                    : (t == 1) ? (float)((double)T_STEPS * BATCH * H2)
                               : (float)((double)T_STEPS * BATCH * H3);
        out[BATCH * 2 + t] = (float)g_cnt[t] / denom;
    }
}

// ---------------- launch --------------------------------------------------------
extern "C" void kernel_launch(void* const* d_in, const int* in_sizes, int n_in,
                              void* d_out, int out_size)
{
    const float* spikes = (const float*)d_in[0];
    const float* W1 = (const float*)d_in[1];
    const float* b1 = (const float*)d_in[2];
    const float* W2 = (const float*)d_in[3];
    const float* b2 = (const float*)d_in[4];
    const float* W3 = (const float*)d_in[5];
    const float* b3 = (const float*)d_in[6];
    const float* Wr = (const float*)d_in[7];
    const float* br = (const float*)d_in[8];
    float* out = (float*)d_out;

    // phase1 needs (512+1)*64*4 = 131,328 B; phase2/3 need 1024*33*4 = 135,168 B
    const int DSMEM = 1024 * SW2 * 4;
    cudaFuncSetAttribute(snn_phased,
                         cudaFuncAttributeMaxDynamicSharedMemorySize, DSMEM);

    init_kernel<<<1, 256>>>();
    {
        int n = T_STEPS * BATCH * 16;
        build_xbits<<<(n + 255) / 256, 256>>>(spikes);
        build_xidx<<<(T_STEPS * BATCH + 255) / 256, 256>>>();
    }
    snn_phased<<<NCTA, 512, DSMEM>>>(W1, b1, W2, b2, W3, b3);
    final_kernel<<<BATCH, 128>>>(Wr, br, out);
}

// round 12
// speedup vs baseline: 31.4041x; 1.0597x over previous
#include <cuda_runtime.h>
#include <cstdint>

#define T_STEPS 200
#define BATCH   256
#define IN_F    512
#define H1      1024
#define H2      1024
#define H3      512
#define NCTA    128
#define SW2     33      // phase-2/3 weight row stride (floats)
#define IDXCAP  544     // per-(t,row) index list capacity (16B-aligned rows)

// ---------------- persistent device state ------------------------------------
__device__ float g_m3sum[BATCH * H3];
__device__ int   g_cnt[3];
__device__ unsigned g_xbits[T_STEPS * BATCH * 16];        // [t][row][16 words]
__device__ unsigned short g_xidx[T_STEPS][BATCH][IDXCAP]; // compacted k lists
__device__ int g_xcnt[T_STEPS][BATCH];                    // padded counts (mult of 8)
__device__ unsigned g_b1[T_STEPS][BATCH][32];             // spk1 history
__device__ unsigned g_b2[T_STEPS][BATCH][32];             // spk2 history
__device__ volatile int g_arrive[NCTA];
__device__ volatile int g_release;

// ---------------- prep ---------------------------------------------------------
__global__ void init_kernel() {
    int i = blockIdx.x * blockDim.x + threadIdx.x;
    if (i < 3) g_cnt[i] = 0;
    if (i < NCTA) g_arrive[i] = 0;
    if (i == 0) g_release = 0;
}

__global__ void build_xbits(const float* __restrict__ s) {
    int j = blockIdx.x * blockDim.x + threadIdx.x;
    if (j < T_STEPS * BATCH * 16) {
        const float4* p = (const float4*)(s + (size_t)j * 32);
        unsigned b = 0;
#pragma unroll
        for (int q = 0; q < 8; q++) {
            float4 v = p[q];
            b |= (v.x > 0.5f ? 1u : 0u) << (4 * q + 0);
            b |= (v.y > 0.5f ? 1u : 0u) << (4 * q + 1);
            b |= (v.z > 0.5f ? 1u : 0u) << (4 * q + 2);
            b |= (v.w > 0.5f ? 1u : 0u) << (4 * q + 3);
        }
        g_xbits[j] = b;
    }
}

// one thread per (t,row): compact active k's (ascending), pad to multiple of 8
__global__ void build_xidx() {
    int id = blockIdx.x * blockDim.x + threadIdx.x;
    if (id >= T_STEPS * BATCH) return;
    int t = id / BATCH, r = id % BATCH;
    const unsigned* wp = &g_xbits[(size_t)id * 16];
    unsigned short* dst = g_xidx[t][r];
    int n = 0;
#pragma unroll
    for (int w = 0; w < 16; w++) {
        unsigned bits = wp[w];
        while (bits) {
            int b = __ffs(bits) - 1;
            bits &= bits - 1;
            dst[n++] = (unsigned short)(w * 32 + b);
        }
    }
    int np = (n + 7) & ~7;
    while (n < np) dst[n++] = (unsigned short)IN_F;   // dummy -> zero weight row
    g_xcnt[t][r] = np;
}

// ---------------- global barrier ----------------------------------------------
__device__ __forceinline__ void gbar(int gen, int cta, int tid) {
    __syncthreads();
    if (tid == 0) { __threadfence(); g_arrive[cta] = gen; }
    if (cta == 0 && tid < 32) {
        for (;;) {
            int v0 = g_arrive[tid];
            int v1 = g_arrive[tid + 32];
            int v2 = g_arrive[tid + 64];
            int v3 = g_arrive[tid + 96];
            if (__all_sync(0xFFFFFFFFu,
                           v0 >= gen && v1 >= gen && v2 >= gen && v3 >= gen))
                break;
        }
        if (tid == 0) { __threadfence(); g_release = gen; }
    }
    if (tid == 0) {
        while (g_release < gen) { }
        __threadfence();
    }
    __syncthreads();
}

// ---------------- LIF scalar step ----------------------------------------------
__device__ __forceinline__ unsigned lif1(float& m, float a, float beta) {
    float reset = (m > 1.0f) ? 1.0f : 0.0f;    // spike(m_prev - 1)
    m = beta * m + a - reset;                  // subtract-reset
    return (m > 1.0f) ? 1u : 0u;               // spike(m_new - 1)
}

// ---------------- THE persistent kernel ----------------------------------------
__global__ void __launch_bounds__(512, 1)
snn_phased(const float* __restrict__ W1, const float* __restrict__ b1,
           const float* __restrict__ W2, const float* __restrict__ b2,
           const float* __restrict__ W3, const float* __restrict__ b3)
{
    extern __shared__ float Wsm[];   // phase1: float2[513][32]; phase2/3: [1024][33]
    __shared__ int sr_[3][16];

    const int tid  = threadIdx.x;
    const int cta  = blockIdx.x;
    const int wid  = tid >> 5;
    const int lane = tid & 31;

    const float BETA1 = 0.81873075307798182f;  // exp(-1/5)
    const float BETA2 = 0.90483741803595957f;  // exp(-1/10)
    const float BETA3 = 0.95122942450071402f;  // exp(-1/20)

    int c1 = 0, c2 = 0, c3 = 0;

    // ================= phase 1: layer 1 (64 cols x 32 rows per CTA) ==========
    {
        float2* Wp2 = (float2*)Wsm;     // Wp2[k*32 + lane] = (W[c0+lane][k], W[c0+32+lane][k])
        const int cb = cta & 15;        // 16 col-blocks of 64
        const int rg = cta >> 4;        // 8 row-groups of 32
        for (int idx = tid; idx < 64 * IN_F; idx += 512) {
            int c = idx >> 9, k = idx & (IN_F - 1);
            Wsm[k * 64 + (c & 31) * 2 + (c >> 5)] =
                W1[(size_t)(cb * 64 + c) * IN_F + k];
        }
        if (tid < 64) Wsm[IN_F * 64 + tid] = 0.f;   // dummy row k = IN_F

        const int r0 = rg * 32 + wid * 2;           // warp owns rows r0, r0+1
        const float bs0 = b1[cb * 64 + lane];
        const float bs1 = b1[cb * 64 + 32 + lane];
        float m[2][2] = {{0.f, 0.f}, {0.f, 0.f}};
        __syncthreads();

        // prefetch t=0 counts + first idx groups (same-address LDG, all lanes)
        int pn[2]; uint4 pg[2];
#pragma unroll
        for (int i = 0; i < 2; i++) {
            pn[i] = __ldcg(&g_xcnt[0][r0 + i]);
            pg[i] = __ldcg((const uint4*)g_xidx[0][r0 + i]);
        }

        for (int t = 0; t < T_STEPS; t++) {
            int  nn[2] = {pn[0], pn[1]};
            uint4 g0[2] = {pg[0], pg[1]};
            if (t + 1 < T_STEPS) {
#pragma unroll
                for (int i = 0; i < 2; i++) {
                    pn[i] = __ldcg(&g_xcnt[t + 1][r0 + i]);
                    pg[i] = __ldcg((const uint4*)g_xidx[t + 1][r0 + i]);
                }
            }
#pragma unroll
            for (int i = 0; i < 2; i++) {
                float a0 = bs0, a1 = bs1;
                const uint4* lp = (const uint4*)g_xidx[t][r0 + i];  // 8 idx/uint4
                const int ng = nn[i] >> 3;
                uint4 g = g0[i];
                for (int j = 0; j < ng; j++) {
                    uint4 gn = g;
                    if (j + 1 < ng) gn = __ldcg(lp + j + 1);
                    unsigned k;
                    float2 w;
#define GATHER(word, sh) \
                    k = ((word) >> (sh)) & 0xFFFFu; \
                    w = Wp2[k * 32 + lane]; \
                    a0 += w.x; a1 += w.y;
                    GATHER(g.x, 0)  GATHER(g.x, 16)
                    GATHER(g.y, 0)  GATHER(g.y, 16)
                    GATHER(g.z, 0)  GATHER(g.z, 16)
                    GATHER(g.w, 0)  GATHER(g.w, 16)
#undef GATHER
                    g = gn;
                }
                unsigned s0 = lif1(m[i][0], a0, BETA1);
                unsigned s1 = lif1(m[i][1], a1, BETA1);
                unsigned w0 = __ballot_sync(0xFFFFFFFFu, s0);
                unsigned w1 = __ballot_sync(0xFFFFFFFFu, s1);
                if (lane == 0) {
                    c1 += __popc(w0) + __popc(w1);
                    *(unsigned long long*)&g_b1[t][r0 + i][cb * 2] =
                        ((unsigned long long)w1 << 32) | w0;
                }
            }
        }
    }
    gbar(1, cta, tid);

    // ================= phase 2: layer 2 (32 cols x 64 rows per CTA) ==========
    {
        const int cb = cta & 31;        // 32 col-blocks of 32
        const int rg = cta >> 5;        // 4 row-groups of 64
        for (int idx = tid; idx < 32 * H1; idx += 512) {
            int n = idx >> 10, k = idx & (H1 - 1);
            Wsm[k * SW2 + n] = W2[(size_t)(cb * 32 + n) * H1 + k];
        }
        const int r0 = rg * 64 + wid * 4;          // warp owns rows r0..r0+3
        const float bsv = b2[cb * 32 + lane];
        float m[4] = {0.f, 0.f, 0.f, 0.f};
        __syncthreads();

        unsigned cur[4];
#pragma unroll
        for (int c = 0; c < 4; c++) cur[c] = __ldcg(&g_b1[0][r0 + c][lane]);
        for (int t = 0; t < T_STEPS; t++) {
            unsigned nxt[4] = {0, 0, 0, 0};
            if (t + 1 < T_STEPS) {
#pragma unroll
                for (int c = 0; c < 4; c++)
                    nxt[c] = __ldcg(&g_b1[t + 1][r0 + c][lane]);
            }
#pragma unroll
            for (int i = 0; i < 4; i++) {
                float a = bsv;
                unsigned nz = __ballot_sync(0xFFFFFFFFu, cur[i] != 0u);
                while (nz) {
                    int w = __ffs(nz) - 1;
                    nz &= nz - 1;
                    unsigned bits = __shfl_sync(0xFFFFFFFFu, cur[i], w);
                    while (bits) {
                        int b = __ffs(bits) - 1;
                        bits &= bits - 1;
                        a += Wsm[(w * 32 + b) * SW2 + lane];
                    }
                }
                unsigned s = lif1(m[i], a, BETA2);
                unsigned w0 = __ballot_sync(0xFFFFFFFFu, s);
                if (lane == 0) {
                    c2 += __popc(w0);
                    g_b2[t][r0 + i][cb] = w0;
                }
            }
#pragma unroll
            for (int c = 0; c < 4; c++) cur[c] = nxt[c];
        }
    }
    gbar(2, cta, tid);

    // ================= phase 3: layer 3 (32 cols x 32 rows per CTA) ==========
    {
        const int cb = cta & 15;        // 16 col-blocks of 32
        const int rg = cta >> 4;        // 8 row-groups of 32
        for (int idx = tid; idx < 32 * H2; idx += 512) {
            int n = idx >> 10, k = idx & (H2 - 1);
            Wsm[k * SW2 + n] = W3[(size_t)(cb * 32 + n) * H2 + k];
        }
        const int r0 = rg * 32 + wid * 2;          // warp owns rows r0, r0+1
        const float bsv = b3[cb * 32 + lane];
        float m[2] = {0.f, 0.f}, ms[2] = {0.f, 0.f};
        __syncthreads();

        unsigned cur[2];
#pragma unroll
        for (int c = 0; c < 2; c++) cur[c] = __ldcg(&g_b2[0][r0 + c][lane]);
        for (int t = 0; t < T_STEPS; t++) {
            unsigned nxt[2] = {0, 0};
            if (t + 1 < T_STEPS) {
#pragma unroll
                for (int c = 0; c < 2; c++)
                    nxt[c] = __ldcg(&g_b2[t + 1][r0 + c][lane]);
            }
#pragma unroll
            for (int i = 0; i < 2; i++) {
                float a = bsv;
                unsigned nz = __ballot_sync(0xFFFFFFFFu, cur[i] != 0u);
                while (nz) {
                    int w = __ffs(nz) - 1;
                    nz &= nz - 1;
                    unsigned bits = __shfl_sync(0xFFFFFFFFu, cur[i], w);
                    while (bits) {
                        int b = __ffs(bits) - 1;
                        bits &= bits - 1;
                        a += Wsm[(w * 32 + b) * SW2 + lane];
                    }
                }
                unsigned s = lif1(m[i], a, BETA3);
                ms[i] += m[i];
                unsigned w0 = __ballot_sync(0xFFFFFFFFu, s);
                if (lane == 0) c3 += __popc(w0);
            }
#pragma unroll
            for (int c = 0; c < 2; c++) cur[c] = nxt[c];
        }
#pragma unroll
        for (int i = 0; i < 2; i++)
            g_m3sum[(size_t)(r0 + i) * H3 + cb * 32 + lane] = ms[i];
    }

    // ---- exact spike counts ----
    if (lane == 0) { sr_[0][wid] = c1; sr_[1][wid] = c2; sr_[2][wid] = c3; }
    __syncthreads();
    if (tid < 3) {
        int s = 0;
#pragma unroll
        for (int w = 0; w < 16; w++) s += sr_[tid][w];
        atomicAdd(&g_cnt[tid], s);
    }
}

// ---------------- readout -------------------------------------------------------
__global__ void final_kernel(const float* __restrict__ Wr,
                             const float* __restrict__ br,
                             float* __restrict__ out)
{
    const int b = blockIdx.x;
    const int t = threadIdx.x;
    float a0 = 0.f, a1 = 0.f;
    for (int j = t; j < H3; j += 128) {
        float v = g_m3sum[(size_t)b * H3 + j] / (float)T_STEPS;
        a0 = fmaf(v, Wr[j],      a0);
        a1 = fmaf(v, Wr[H3 + j], a1);
    }
    __shared__ float s0[128], s1[128];
    s0[t] = a0; s1[t] = a1;
    __syncthreads();
    for (int o = 64; o > 0; o >>= 1) {
        if (t < o) { s0[t] += s0[t + o]; s1[t] += s1[t + o]; }
        __syncthreads();
    }
    if (t == 0) {
        out[b * 2 + 0] = s0[0] + br[0];
        out[b * 2 + 1] = s1[0] + br[1];
    }
    if (b == 0 && t < 3) {
        float denom = (t == 0) ? (float)((double)T_STEPS * BATCH * H1)
                    : (t == 1) ? (float)((double)T_STEPS * BATCH * H2)
                               : (float)((double)T_STEPS * BATCH * H3);
        out[BATCH * 2 + t] = (float)g_cnt[t] / denom;
    }
}

// ---------------- launch --------------------------------------------------------
extern "C" void kernel_launch(void* const* d_in, const int* in_sizes, int n_in,
                              void* d_out, int out_size)
{
    const float* spikes = (const float*)d_in[0];
    const float* W1 = (const float*)d_in[1];
    const float* b1 = (const float*)d_in[2];
    const float* W2 = (const float*)d_in[3];
    const float* b2 = (const float*)d_in[4];
    const float* W3 = (const float*)d_in[5];
    const float* b3 = (const float*)d_in[6];
    const float* Wr = (const float*)d_in[7];
    const float* br = (const float*)d_in[8];
    float* out = (float*)d_out;

    // phase1 needs (512+1)*64*4 = 131,328 B; phase2/3 need 1024*33*4 = 135,168 B
    const int DSMEM = 1024 * SW2 * 4;
    cudaFuncSetAttribute(snn_phased,
                         cudaFuncAttributeMaxDynamicSharedMemorySize, DSMEM);

    init_kernel<<<1, 256>>>();
    {
        int n = T_STEPS * BATCH * 16;
        build_xbits<<<(n + 255) / 256, 256>>>(spikes);
        build_xidx<<<(T_STEPS * BATCH + 255) / 256, 256>>>();
    }
    snn_phased<<<NCTA, 512, DSMEM>>>(W1, b1, W2, b2, W3, b3);
    final_kernel<<<BATCH, 128>>>(Wr, br, out);
}